// round 1
// baseline (speedup 1.0000x reference)
#include <cuda_runtime.h>
#include <math.h>

// ---------------------------------------------------------------------------
// Model dims (fixed for this problem)
// ---------------------------------------------------------------------------
#define NP   4096      // B*T tokens
#define BB   4
#define TT   1024
#define DM   1024
#define HH   16
#define HS   64
#define DFF  4096
#define VV   32000
#define LL   6
#define DBK  64
#define DIN  1088      // D + Db

// ---------------------------------------------------------------------------
// Scratch (device globals; no allocation allowed)
// ---------------------------------------------------------------------------
__device__ float g_x [NP * DM];
__device__ float g_h [NP * DM];
__device__ float g_q [NP * DM];
__device__ float g_k [NP * DM];
__device__ float g_v [NP * DM];
__device__ float g_ao[NP * DM];
__device__ float g_h2[NP * DIN];
__device__ float g_ff[NP * DFF];
__device__ float g_rowloss[NP];

// ---------------------------------------------------------------------------
// Block reductions
// ---------------------------------------------------------------------------
__device__ __forceinline__ float blockReduceSum(float v) {
    __shared__ float sm[33];
    int lane = threadIdx.x & 31, w = threadIdx.x >> 5;
#pragma unroll
    for (int o = 16; o; o >>= 1) v += __shfl_xor_sync(0xffffffffu, v, o);
    if (lane == 0) sm[w] = v;
    __syncthreads();
    if (w == 0) {
        v = (lane < (blockDim.x >> 5)) ? sm[lane] : 0.f;
#pragma unroll
        for (int o = 16; o; o >>= 1) v += __shfl_xor_sync(0xffffffffu, v, o);
        if (lane == 0) sm[32] = v;
    }
    __syncthreads();
    return sm[32];
}

__device__ __forceinline__ float blockReduceMax(float v) {
    __shared__ float sm[33];
    int lane = threadIdx.x & 31, w = threadIdx.x >> 5;
#pragma unroll
    for (int o = 16; o; o >>= 1) v = fmaxf(v, __shfl_xor_sync(0xffffffffu, v, o));
    if (lane == 0) sm[w] = v;
    __syncthreads();
    if (w == 0) {
        v = (lane < (blockDim.x >> 5)) ? sm[lane] : -1e30f;
#pragma unroll
        for (int o = 16; o; o >>= 1) v = fmaxf(v, __shfl_xor_sync(0xffffffffu, v, o));
        if (lane == 0) sm[32] = v;
    }
    __syncthreads();
    return sm[32];
}

// ---------------------------------------------------------------------------
// Embedding: x = tok_table[idx] + pos_table[t]
// ---------------------------------------------------------------------------
__global__ void embed_kernel(const int* __restrict__ idx,
                             const float* __restrict__ tok,
                             const float* __restrict__ pos) {
    int gid = blockIdx.x * 256 + threadIdx.x;       // over NP*DM
    int n = gid >> 10, d = gid & 1023;
    int t = n & (TT - 1);
    g_x[gid] = tok[(size_t)idx[n] * DM + d] + pos[t * DM + d];
}

// Fill the constant book columns of h2 (cols [1024,1088)) once.
__global__ void book_kernel(const int* __restrict__ ibx,
                            const float* __restrict__ book) {
    int gid = blockIdx.x * 256 + threadIdx.x;       // over NP*DBK
    int n = gid >> 6, d = gid & 63, b = n >> 10;
    g_h2[(size_t)n * DIN + DM + d] = book[ibx[b] * DBK + d];
}

// ---------------------------------------------------------------------------
// LayerNorm: one block per row (D=1024, 256 threads * float4)
// ---------------------------------------------------------------------------
__global__ __launch_bounds__(256) void ln_kernel(const float* __restrict__ x,
                                                 const float* __restrict__ sc,
                                                 const float* __restrict__ bi,
                                                 float* __restrict__ y, int ldo) {
    int row = blockIdx.x, tid = threadIdx.x;
    float4 v = ((const float4*)(x + (size_t)row * DM))[tid];
    float sum = blockReduceSum(v.x + v.y + v.z + v.w);
    float mu = sum * (1.f / DM);
    float dx = v.x - mu, dy = v.y - mu, dz = v.z - mu, dw = v.w - mu;
    float sq = blockReduceSum(dx * dx + dy * dy + dz * dz + dw * dw);
    float rstd = rsqrtf(sq * (1.f / DM) + 1e-5f);
    int c = tid * 4;
    const float4 s4 = ((const float4*)sc)[tid];
    const float4 b4 = ((const float4*)bi)[tid];
    float* yr = y + (size_t)row * ldo + c;
    yr[0] = dx * rstd * s4.x + b4.x;
    yr[1] = dy * rstd * s4.y + b4.y;
    yr[2] = dz * rstd * s4.z + b4.z;
    yr[3] = dw * rstd * s4.w + b4.w;
}

// ---------------------------------------------------------------------------
// SGEMM: C[M,N] = A[M,K] @ B[K,N] (+bias) (+relu) (+residual)
// 64x64 block tile, BK=16, 256 threads, 4x4 per thread.
// M,N multiples of 64; K multiple of 16. All row-major.
// ---------------------------------------------------------------------------
__global__ __launch_bounds__(256) void sgemm_kernel(
    const float* __restrict__ A, const float* __restrict__ B,
    const float* __restrict__ bias, const float* __restrict__ res,
    float* __restrict__ C, int M, int N, int K, int relu) {
    __shared__ float As[16][64];
    __shared__ float Bs[16][64];
    int bx = blockIdx.x, by = blockIdx.y;
    int tid = threadIdx.x;
    int tx = tid & 15, ty = tid >> 4;

    const float* Ablk = A + (size_t)by * 64 * K;
    const float* Bblk = B + (size_t)bx * 64;

    float acc[4][4];
#pragma unroll
    for (int i = 0; i < 4; i++)
#pragma unroll
        for (int j = 0; j < 4; j++) acc[i][j] = 0.f;

    int arow = tid >> 2, acol = (tid & 3) * 4;
    int brow = tid >> 4, bcol = (tid & 15) * 4;

    for (int k0 = 0; k0 < K; k0 += 16) {
        float4 a4 = *(const float4*)(Ablk + (size_t)arow * K + k0 + acol);
        As[acol + 0][arow] = a4.x;
        As[acol + 1][arow] = a4.y;
        As[acol + 2][arow] = a4.z;
        As[acol + 3][arow] = a4.w;
        float4 b4 = *(const float4*)(Bblk + (size_t)(k0 + brow) * N + bcol);
        *(float4*)&Bs[brow][bcol] = b4;
        __syncthreads();
#pragma unroll
        for (int kk = 0; kk < 16; kk++) {
            float ar[4], br[4];
#pragma unroll
            for (int i = 0; i < 4; i++) ar[i] = As[kk][ty * 4 + i];
#pragma unroll
            for (int j = 0; j < 4; j++) br[j] = Bs[kk][tx * 4 + j];
#pragma unroll
            for (int i = 0; i < 4; i++)
#pragma unroll
                for (int j = 0; j < 4; j++) acc[i][j] += ar[i] * br[j];
        }
        __syncthreads();
    }

    int row0 = by * 64 + ty * 4;
    int col0 = bx * 64 + tx * 4;
#pragma unroll
    for (int i = 0; i < 4; i++) {
        size_t rbase = (size_t)(row0 + i) * N + col0;
#pragma unroll
        for (int j = 0; j < 4; j++) {
            float val = acc[i][j];
            if (bias) val += bias[col0 + j];
            if (relu) val = fmaxf(val, 0.f);
            if (res) val += res[rbase + j];
            C[rbase + j] = val;
        }
    }
}

// ---------------------------------------------------------------------------
// Flash attention (fp32): grid (T/64, H, B), 256 threads, 64x64 tiles,
// online softmax, O accumulated in registers (4x4/thread).
// ---------------------------------------------------------------------------
#define ATTN_SMEM ((2 * 64 * 65 + 64 * 64) * 4)

__global__ __launch_bounds__(256) void attn_kernel(const float* __restrict__ q,
                                                   const float* __restrict__ k,
                                                   const float* __restrict__ v,
                                                   float* __restrict__ o) {
    extern __shared__ float sm[];
    float* Qs = sm;                 // [64][65]
    float* Ks = sm + 64 * 65;       // [64][65], reused for P
    float* Vs = sm + 2 * 64 * 65;   // [64][64]

    int qt = blockIdx.x, h = blockIdx.y, b = blockIdx.z;
    int tid = threadIdx.x, tx = tid & 15, ty = tid >> 4;
    int rb = b * TT;
    int colbase = h * HS;

    // load Q tile
#pragma unroll
    for (int it = 0; it < 4; it++) {
        int lin = it * 1024 + tid * 4;
        int r = lin >> 6, c = lin & 63;
        float4 t4 = *(const float4*)(q + (size_t)(rb + qt * 64 + r) * DM + colbase + c);
        Qs[r * 65 + c + 0] = t4.x;
        Qs[r * 65 + c + 1] = t4.y;
        Qs[r * 65 + c + 2] = t4.z;
        Qs[r * 65 + c + 3] = t4.w;
    }

    float m_i[4], l_i[4], oacc[4][4];
#pragma unroll
    for (int i = 0; i < 4; i++) {
        m_i[i] = -1e30f;
        l_i[i] = 0.f;
#pragma unroll
        for (int j = 0; j < 4; j++) oacc[i][j] = 0.f;
    }

    for (int jt = 0; jt <= qt; jt++) {
        __syncthreads();   // prior iter done with Ks/Vs; Q load visible (1st iter)
        // load K, V tiles
#pragma unroll
        for (int it = 0; it < 4; it++) {
            int lin = it * 1024 + tid * 4;
            int r = lin >> 6, c = lin & 63;
            size_t goff = (size_t)(rb + jt * 64 + r) * DM + colbase + c;
            float4 k4 = *(const float4*)(k + goff);
            Ks[r * 65 + c + 0] = k4.x;
            Ks[r * 65 + c + 1] = k4.y;
            Ks[r * 65 + c + 2] = k4.z;
            Ks[r * 65 + c + 3] = k4.w;
            float4 v4 = *(const float4*)(v + goff);
            *(float4*)&Vs[r * 64 + c] = v4;
        }
        __syncthreads();

        // S = Q K^T
        float s[4][4];
#pragma unroll
        for (int i = 0; i < 4; i++)
#pragma unroll
            for (int j = 0; j < 4; j++) s[i][j] = 0.f;
        for (int d = 0; d < 64; d++) {
            float ar[4], br[4];
#pragma unroll
            for (int i = 0; i < 4; i++) ar[i] = Qs[(ty * 4 + i) * 65 + d];
#pragma unroll
            for (int j = 0; j < 4; j++) br[j] = Ks[(tx * 4 + j) * 65 + d];
#pragma unroll
            for (int i = 0; i < 4; i++)
#pragma unroll
                for (int j = 0; j < 4; j++) s[i][j] += ar[i] * br[j];
        }
        // scale + causal mask
#pragma unroll
        for (int i = 0; i < 4; i++) {
            int qi = qt * 64 + ty * 4 + i;
#pragma unroll
            for (int j = 0; j < 4; j++) {
                int kj = jt * 64 + tx * 4 + j;
                s[i][j] = (kj <= qi) ? s[i][j] * 0.125f : -1e30f;
            }
        }
        // online softmax update per row
        float corr[4];
#pragma unroll
        for (int i = 0; i < 4; i++) {
            float mx = fmaxf(fmaxf(s[i][0], s[i][1]), fmaxf(s[i][2], s[i][3]));
#pragma unroll
            for (int off = 8; off; off >>= 1)
                mx = fmaxf(mx, __shfl_xor_sync(0xffffffffu, mx, off));
            float mnew = fmaxf(m_i[i], mx);
            float ls = 0.f;
#pragma unroll
            for (int j = 0; j < 4; j++) {
                s[i][j] = __expf(s[i][j] - mnew);
                ls += s[i][j];
            }
#pragma unroll
            for (int off = 8; off; off >>= 1)
                ls += __shfl_xor_sync(0xffffffffu, ls, off);
            corr[i] = __expf(m_i[i] - mnew);
            l_i[i] = l_i[i] * corr[i] + ls;
            m_i[i] = mnew;
        }
        __syncthreads();   // done reading Ks as K
        // store P into Ks
#pragma unroll
        for (int i = 0; i < 4; i++)
#pragma unroll
            for (int j = 0; j < 4; j++)
                Ks[(ty * 4 + i) * 65 + tx * 4 + j] = s[i][j];
        __syncthreads();
        // O = O*corr + P @ V
#pragma unroll
        for (int i = 0; i < 4; i++)
#pragma unroll
            for (int j = 0; j < 4; j++) oacc[i][j] *= corr[i];
        for (int kk = 0; kk < 64; kk++) {
            float ar[4], br[4];
#pragma unroll
            for (int i = 0; i < 4; i++) ar[i] = Ks[(ty * 4 + i) * 65 + kk];
#pragma unroll
            for (int j = 0; j < 4; j++) br[j] = Vs[kk * 64 + tx * 4 + j];
#pragma unroll
            for (int i = 0; i < 4; i++)
#pragma unroll
                for (int j = 0; j < 4; j++) oacc[i][j] += ar[i] * br[j];
        }
    }

    // write O / l
#pragma unroll
    for (int i = 0; i < 4; i++) {
        float inv = 1.f / l_i[i];
        size_t rbase = (size_t)(rb + qt * 64 + ty * 4 + i) * DM + colbase + tx * 4;
#pragma unroll
        for (int j = 0; j < 4; j++) o[rbase + j] = oacc[i][j] * inv;
    }
}

// ---------------------------------------------------------------------------
// Loss: per-row -logp[target], then deterministic mean
// ---------------------------------------------------------------------------
__global__ __launch_bounds__(256) void loss_row_kernel(const float* __restrict__ logits,
                                                       const int* __restrict__ targets) {
    int row = blockIdx.x, tid = threadIdx.x;
    const float* lr = logits + (size_t)row * VV;
    float mx = -1e30f;
    for (int c = tid; c < VV; c += 256) mx = fmaxf(mx, lr[c]);
    mx = blockReduceMax(mx);
    float s = 0.f;
    for (int c = tid; c < VV; c += 256) s += __expf(lr[c] - mx);
    s = blockReduceSum(s);
    if (tid == 0)
        g_rowloss[row] = (mx + logf(s)) - lr[targets[row]];
}

__global__ __launch_bounds__(256) void loss_final_kernel(float* __restrict__ out) {
    float s = 0.f;
    for (int i = threadIdx.x; i < NP; i += 256) s += g_rowloss[i];
    s = blockReduceSum(s);
    if (threadIdx.x == 0) out[0] = s * (1.f / NP);
}

// ---------------------------------------------------------------------------
// Host launcher
// ---------------------------------------------------------------------------
extern "C" void kernel_launch(void* const* d_in, const int* in_sizes, int n_in,
                              void* d_out, int out_size) {
    const int*   idx  = (const int*)d_in[0];
    const int*   ibx  = (const int*)d_in[1];
    const int*   tgt  = (const int*)d_in[2];
    const float* tok  = (const float*)d_in[3];
    const float* pos  = (const float*)d_in[4];
    const float* book = (const float*)d_in[5];
    const float* Wq   = (const float*)d_in[6];
    const float* Wk   = (const float*)d_in[7];
    const float* Wv   = (const float*)d_in[8];
    const float* Wo   = (const float*)d_in[9];
    const float* bo   = (const float*)d_in[10];
    const float* ln1s = (const float*)d_in[11];
    const float* ln1b = (const float*)d_in[12];
    const float* ln2s = (const float*)d_in[13];
    const float* ln2b = (const float*)d_in[14];
    const float* W1   = (const float*)d_in[15];
    const float* b1   = (const float*)d_in[16];
    const float* W2   = (const float*)d_in[17];
    const float* b2   = (const float*)d_in[18];
    const float* lnfs = (const float*)d_in[19];
    const float* lnfb = (const float*)d_in[20];
    const float* Wh   = (const float*)d_in[21];
    const float* bh   = (const float*)d_in[22];
    float* out = (float*)d_out;

    float *x, *h, *q, *k, *v, *ao, *h2, *ff;
    cudaGetSymbolAddress((void**)&x,  g_x);
    cudaGetSymbolAddress((void**)&h,  g_h);
    cudaGetSymbolAddress((void**)&q,  g_q);
    cudaGetSymbolAddress((void**)&k,  g_k);
    cudaGetSymbolAddress((void**)&v,  g_v);
    cudaGetSymbolAddress((void**)&ao, g_ao);
    cudaGetSymbolAddress((void**)&h2, g_h2);
    cudaGetSymbolAddress((void**)&ff, g_ff);

    cudaFuncSetAttribute(attn_kernel, cudaFuncAttributeMaxDynamicSharedMemorySize,
                         ATTN_SMEM);

    embed_kernel<<<NP * DM / 256, 256>>>(idx, tok, pos);
    book_kernel<<<NP * DBK / 256, 256>>>(ibx, book);

    dim3 gDD(DM / 64, NP / 64);
    for (int l = 0; l < LL; l++) {
        ln_kernel<<<NP, 256>>>(x, ln1s + l * DM, ln1b + l * DM, h, DM);
        sgemm_kernel<<<gDD, 256>>>(h, Wq + (size_t)l * DM * DM, nullptr, nullptr, q,
                                   NP, DM, DM, 0);
        sgemm_kernel<<<gDD, 256>>>(h, Wk + (size_t)l * DM * DM, nullptr, nullptr, k,
                                   NP, DM, DM, 0);
        sgemm_kernel<<<gDD, 256>>>(h, Wv + (size_t)l * DM * DM, nullptr, nullptr, v,
                                   NP, DM, DM, 0);
        attn_kernel<<<dim3(TT / 64, HH, BB), 256, ATTN_SMEM>>>(q, k, v, ao);
        sgemm_kernel<<<gDD, 256>>>(ao, Wo + (size_t)l * DM * DM, bo + l * DM, x, x,
                                   NP, DM, DM, 0);
        ln_kernel<<<NP, 256>>>(x, ln2s + l * DM, ln2b + l * DM, h2, DIN);
        sgemm_kernel<<<dim3(DFF / 64, NP / 64), 256>>>(
            h2, W1 + (size_t)l * DIN * DFF, b1 + l * DFF, nullptr, ff,
            NP, DFF, DIN, 1);
        sgemm_kernel<<<gDD, 256>>>(ff, W2 + (size_t)l * DFF * DM, b2 + l * DM, x, x,
                                   NP, DM, DFF, 0);
    }

    ln_kernel<<<NP, 256>>>(x, lnfs, lnfb, h, DM);
    sgemm_kernel<<<dim3(VV / 64, NP / 64), 256>>>(h, Wh, bh, nullptr, out,
                                                  NP, VV, DM, 0);
    loss_row_kernel<<<NP, 256>>>(out, tgt);
    if (out_size > NP * VV)
        loss_final_kernel<<<1, 256>>>(out + (size_t)NP * VV);
}

// round 2
// speedup vs baseline: 2.6841x; 2.6841x over previous
#include <cuda_runtime.h>
#include <math.h>
#include <stdint.h>

// ---------------------------------------------------------------------------
// Model dims (fixed for this problem)
// ---------------------------------------------------------------------------
#define NP   4096      // B*T tokens
#define BB   4
#define TT   1024
#define DM   1024
#define HH   16
#define HS   64
#define DFF  4096
#define VV   32000
#define LL   6
#define DBK  64
#define DIN  1088      // D + Db

// ---------------------------------------------------------------------------
// Scratch (device globals; no allocation allowed)
// ---------------------------------------------------------------------------
__device__ float g_x [NP * DM];
__device__ float g_h [NP * DM];
__device__ float g_q [NP * DM];
__device__ float g_k [NP * DM];
__device__ float g_v [NP * DM];
__device__ float g_ao[NP * DM];
__device__ float g_h2[NP * DIN];
__device__ float g_ff[NP * DFF];
__device__ float g_rowloss[NP];

// ---------------------------------------------------------------------------
// Helpers
// ---------------------------------------------------------------------------
__device__ __forceinline__ uint32_t f2tf32(float x) {
    uint32_t u;
    asm("cvt.rna.tf32.f32 %0, %1;" : "=r"(u) : "f"(x));
    return u;
}

__device__ __forceinline__ float blockReduceSum(float v) {
    __shared__ float sm[33];
    int lane = threadIdx.x & 31, w = threadIdx.x >> 5;
#pragma unroll
    for (int o = 16; o; o >>= 1) v += __shfl_xor_sync(0xffffffffu, v, o);
    if (lane == 0) sm[w] = v;
    __syncthreads();
    if (w == 0) {
        v = (lane < (blockDim.x >> 5)) ? sm[lane] : 0.f;
#pragma unroll
        for (int o = 16; o; o >>= 1) v += __shfl_xor_sync(0xffffffffu, v, o);
        if (lane == 0) sm[32] = v;
    }
    __syncthreads();
    return sm[32];
}

__device__ __forceinline__ float blockReduceMax(float v) {
    __shared__ float sm[33];
    int lane = threadIdx.x & 31, w = threadIdx.x >> 5;
#pragma unroll
    for (int o = 16; o; o >>= 1) v = fmaxf(v, __shfl_xor_sync(0xffffffffu, v, o));
    if (lane == 0) sm[w] = v;
    __syncthreads();
    if (w == 0) {
        v = (lane < (blockDim.x >> 5)) ? sm[lane] : -1e30f;
#pragma unroll
        for (int o = 16; o; o >>= 1) v = fmaxf(v, __shfl_xor_sync(0xffffffffu, v, o));
        if (lane == 0) sm[32] = v;
    }
    __syncthreads();
    return sm[32];
}

// ---------------------------------------------------------------------------
// Embedding: x = tok_table[idx] + pos_table[t]
// ---------------------------------------------------------------------------
__global__ void embed_kernel(const int* __restrict__ idx,
                             const float* __restrict__ tok,
                             const float* __restrict__ pos) {
    int gid = blockIdx.x * 256 + threadIdx.x;       // over NP*DM
    int n = gid >> 10, d = gid & 1023;
    int t = n & (TT - 1);
    g_x[gid] = tok[(size_t)idx[n] * DM + d] + pos[t * DM + d];
}

// Fill the constant book columns of h2 (cols [1024,1088)) once.
__global__ void book_kernel(const int* __restrict__ ibx,
                            const float* __restrict__ book) {
    int gid = blockIdx.x * 256 + threadIdx.x;       // over NP*DBK
    int n = gid >> 6, d = gid & 63, b = n >> 10;
    g_h2[(size_t)n * DIN + DM + d] = book[ibx[b] * DBK + d];
}

// ---------------------------------------------------------------------------
// LayerNorm: one block per row (D=1024, 256 threads * float4)
// ---------------------------------------------------------------------------
__global__ __launch_bounds__(256) void ln_kernel(const float* __restrict__ x,
                                                 const float* __restrict__ sc,
                                                 const float* __restrict__ bi,
                                                 float* __restrict__ y, int ldo) {
    int row = blockIdx.x, tid = threadIdx.x;
    float4 v = ((const float4*)(x + (size_t)row * DM))[tid];
    float sum = blockReduceSum(v.x + v.y + v.z + v.w);
    float mu = sum * (1.f / DM);
    float dx = v.x - mu, dy = v.y - mu, dz = v.z - mu, dw = v.w - mu;
    float sq = blockReduceSum(dx * dx + dy * dy + dz * dz + dw * dw);
    float rstd = rsqrtf(sq * (1.f / DM) + 1e-5f);
    int c = tid * 4;
    const float4 s4 = ((const float4*)sc)[tid];
    const float4 b4 = ((const float4*)bi)[tid];
    float* yr = y + (size_t)row * ldo + c;
    yr[0] = dx * rstd * s4.x + b4.x;
    yr[1] = dy * rstd * s4.y + b4.y;
    yr[2] = dz * rstd * s4.z + b4.z;
    yr[3] = dw * rstd * s4.w + b4.w;
}

// ---------------------------------------------------------------------------
// TF32 tensor-core GEMM: C[M,N] = A[M,K] @ B[K,N] (+bias) (+relu) (+residual)
// Block tile 128x128, BK=16, 256 threads (8 warps, warp tile 32x64),
// double-buffered smem. A stored k-major with XOR swizzle; B padded stride 136.
// M,N multiples of 128; K multiple of 16. All row-major fp32 in gmem.
// ---------------------------------------------------------------------------
#define MMA_TF32(d, a, b)                                                      \
    asm volatile(                                                              \
        "mma.sync.aligned.m16n8k8.row.col.f32.tf32.tf32.f32 "                  \
        "{%0,%1,%2,%3}, {%4,%5,%6,%7}, {%8,%9}, {%0,%1,%2,%3};\n"              \
        : "+f"(d[0]), "+f"(d[1]), "+f"(d[2]), "+f"(d[3])                       \
        : "r"(a[0]), "r"(a[1]), "r"(a[2]), "r"(a[3]), "r"(b[0]), "r"(b[1]))

// swizzle for A smem column index: depends on k (row) only
__device__ __forceinline__ int a_swz(int k) {
    return (((k & 3) ^ ((k >> 2) & 3)) << 3);
}

__global__ __launch_bounds__(256, 2) void tgemm_kernel(
    const float* __restrict__ A, const float* __restrict__ B,
    const float* __restrict__ bias, const float* __restrict__ res,
    float* __restrict__ C, int M, int N, int K, int relu) {
    __shared__ float As[2][16 * 128];   // [k][m ^ swz(k)]
    __shared__ float Bs[2][16 * 136];   // [k][n], padded

    const int tid = threadIdx.x;
    const int lane = tid & 31, wid = tid >> 5;
    const int g = lane >> 2, tg = lane & 3;
    const int wm = (wid >> 1) * 32, wn = (wid & 1) * 64;
    const int m0 = blockIdx.y * 128, n0 = blockIdx.x * 128;

    // A global-load mapping: coalesced. row pair (arow, arow+64), 4 float4/row
    const int arow = tid >> 2;        // 0..63
    const int akc  = tid & 3;         // which float4 within the 16-float k-row
    // B global-load mapping: rows (brow, brow+8), cols lane*4
    const int brow = tid >> 5;        // 0..7
    const int bcol = lane * 4;

    float acc[2][8][4];
#pragma unroll
    for (int i = 0; i < 2; i++)
#pragma unroll
        for (int j = 0; j < 8; j++)
#pragma unroll
            for (int c = 0; c < 4; c++) acc[i][j][c] = 0.f;

    const int KT = K >> 4;
    float4 av[2], bv[2];

    // ---- prologue: tile 0 ----
    {
        const float* Ap0 = A + (size_t)(m0 + arow) * K + akc * 4;
        const float* Ap1 = A + (size_t)(m0 + arow + 64) * K + akc * 4;
        av[0] = *(const float4*)Ap0;
        av[1] = *(const float4*)Ap1;
        const float* Bp0 = B + (size_t)brow * N + n0 + bcol;
        const float* Bp1 = B + (size_t)(brow + 8) * N + n0 + bcol;
        bv[0] = *(const float4*)Bp0;
        bv[1] = *(const float4*)Bp1;
#pragma unroll
        for (int it = 0; it < 2; it++) {
            int r = arow + it * 64;
            float vv[4] = {av[it].x, av[it].y, av[it].z, av[it].w};
#pragma unroll
            for (int j = 0; j < 4; j++) {
                int k = akc * 4 + j;
                As[0][k * 128 + (r ^ a_swz(k))] = __uint_as_float(f2tf32(vv[j]));
            }
            int kr = brow + it * 8;
            float* bd = &Bs[0][kr * 136 + bcol];
            float wv[4] = {bv[it].x, bv[it].y, bv[it].z, bv[it].w};
#pragma unroll
            for (int j = 0; j < 4; j++) bd[j] = __uint_as_float(f2tf32(wv[j]));
        }
        __syncthreads();
    }

    int buf = 0;
    for (int kt = 0; kt < KT; kt++) {
        if (kt + 1 < KT) {
            int k0 = (kt + 1) * 16;
            av[0] = *(const float4*)(A + (size_t)(m0 + arow) * K + k0 + akc * 4);
            av[1] = *(const float4*)(A + (size_t)(m0 + arow + 64) * K + k0 + akc * 4);
            bv[0] = *(const float4*)(B + (size_t)(k0 + brow) * N + n0 + bcol);
            bv[1] = *(const float4*)(B + (size_t)(k0 + brow + 8) * N + n0 + bcol);
        }

        // ---- compute on buf ----
        const float* Ab = &As[buf][0];
        const float* Bb = &Bs[buf][0];
#pragma unroll
        for (int ks = 0; ks < 2; ks++) {
            const int kb = ks * 8;
            const int k0r = kb + tg, k1r = kb + tg + 4;
            const int sw0 = a_swz(k0r), sw1 = a_swz(k1r);
            uint32_t af[2][4];
#pragma unroll
            for (int i = 0; i < 2; i++) {
                int m = wm + i * 16 + g;
                af[i][0] = __float_as_uint(Ab[k0r * 128 + (m ^ sw0)]);
                af[i][1] = __float_as_uint(Ab[k0r * 128 + ((m + 8) ^ sw0)]);
                af[i][2] = __float_as_uint(Ab[k1r * 128 + (m ^ sw1)]);
                af[i][3] = __float_as_uint(Ab[k1r * 128 + ((m + 8) ^ sw1)]);
            }
            uint32_t bf[8][2];
#pragma unroll
            for (int j = 0; j < 8; j++) {
                int n = wn + j * 8 + g;
                bf[j][0] = __float_as_uint(Bb[k0r * 136 + n]);
                bf[j][1] = __float_as_uint(Bb[k1r * 136 + n]);
            }
#pragma unroll
            for (int i = 0; i < 2; i++)
#pragma unroll
                for (int j = 0; j < 8; j++) MMA_TF32(acc[i][j], af[i], bf[j]);
        }

        if (kt + 1 < KT) {
            int nb = buf ^ 1;
#pragma unroll
            for (int it = 0; it < 2; it++) {
                int r = arow + it * 64;
                float vv[4] = {av[it].x, av[it].y, av[it].z, av[it].w};
#pragma unroll
                for (int j = 0; j < 4; j++) {
                    int k = akc * 4 + j;
                    As[nb][k * 128 + (r ^ a_swz(k))] =
                        __uint_as_float(f2tf32(vv[j]));
                }
                int kr = brow + it * 8;
                float* bd = &Bs[nb][kr * 136 + bcol];
                float wv[4] = {bv[it].x, bv[it].y, bv[it].z, bv[it].w};
#pragma unroll
                for (int j = 0; j < 4; j++)
                    bd[j] = __uint_as_float(f2tf32(wv[j]));
            }
        }
        __syncthreads();
        buf ^= 1;
    }

    // ---- epilogue ----
#pragma unroll
    for (int i = 0; i < 2; i++) {
        int r0 = m0 + wm + i * 16 + g;
#pragma unroll
        for (int j = 0; j < 8; j++) {
            int c0 = n0 + wn + j * 8 + tg * 2;
            float v0 = acc[i][j][0], v1 = acc[i][j][1];
            float v2 = acc[i][j][2], v3 = acc[i][j][3];
            if (bias) {
                float b0 = bias[c0], b1 = bias[c0 + 1];
                v0 += b0; v1 += b1; v2 += b0; v3 += b1;
            }
            if (relu) {
                v0 = fmaxf(v0, 0.f); v1 = fmaxf(v1, 0.f);
                v2 = fmaxf(v2, 0.f); v3 = fmaxf(v3, 0.f);
            }
            size_t o0 = (size_t)r0 * N + c0;
            size_t o1 = (size_t)(r0 + 8) * N + c0;
            if (res) {
                v0 += res[o0]; v1 += res[o0 + 1];
                v2 += res[o1]; v3 += res[o1 + 1];
            }
            C[o0] = v0; C[o0 + 1] = v1;
            C[o1] = v2; C[o1 + 1] = v3;
        }
    }
}

// ---------------------------------------------------------------------------
// Flash attention (fp32): grid (T/64, H, B), 256 threads, 64x64 tiles,
// online softmax, O accumulated in registers (4x4/thread).
// ---------------------------------------------------------------------------
#define ATTN_SMEM ((2 * 64 * 65 + 64 * 64) * 4)

__global__ __launch_bounds__(256) void attn_kernel(const float* __restrict__ q,
                                                   const float* __restrict__ k,
                                                   const float* __restrict__ v,
                                                   float* __restrict__ o) {
    extern __shared__ float sm[];
    float* Qs = sm;                 // [64][65]
    float* Ks = sm + 64 * 65;       // [64][65], reused for P
    float* Vs = sm + 2 * 64 * 65;   // [64][64]

    int qt = blockIdx.x, h = blockIdx.y, b = blockIdx.z;
    int tid = threadIdx.x, tx = tid & 15, ty = tid >> 4;
    int rb = b * TT;
    int colbase = h * HS;

#pragma unroll
    for (int it = 0; it < 4; it++) {
        int lin = it * 1024 + tid * 4;
        int r = lin >> 6, c = lin & 63;
        float4 t4 = *(const float4*)(q + (size_t)(rb + qt * 64 + r) * DM + colbase + c);
        Qs[r * 65 + c + 0] = t4.x;
        Qs[r * 65 + c + 1] = t4.y;
        Qs[r * 65 + c + 2] = t4.z;
        Qs[r * 65 + c + 3] = t4.w;
    }

    float m_i[4], l_i[4], oacc[4][4];
#pragma unroll
    for (int i = 0; i < 4; i++) {
        m_i[i] = -1e30f;
        l_i[i] = 0.f;
#pragma unroll
        for (int j = 0; j < 4; j++) oacc[i][j] = 0.f;
    }

    for (int jt = 0; jt <= qt; jt++) {
        __syncthreads();
#pragma unroll
        for (int it = 0; it < 4; it++) {
            int lin = it * 1024 + tid * 4;
            int r = lin >> 6, c = lin & 63;
            size_t goff = (size_t)(rb + jt * 64 + r) * DM + colbase + c;
            float4 k4 = *(const float4*)(k + goff);
            Ks[r * 65 + c + 0] = k4.x;
            Ks[r * 65 + c + 1] = k4.y;
            Ks[r * 65 + c + 2] = k4.z;
            Ks[r * 65 + c + 3] = k4.w;
            float4 v4 = *(const float4*)(v + goff);
            *(float4*)&Vs[r * 64 + c] = v4;
        }
        __syncthreads();

        float s[4][4];
#pragma unroll
        for (int i = 0; i < 4; i++)
#pragma unroll
            for (int j = 0; j < 4; j++) s[i][j] = 0.f;
        for (int d = 0; d < 64; d++) {
            float ar[4], br[4];
#pragma unroll
            for (int i = 0; i < 4; i++) ar[i] = Qs[(ty * 4 + i) * 65 + d];
#pragma unroll
            for (int j = 0; j < 4; j++) br[j] = Ks[(tx * 4 + j) * 65 + d];
#pragma unroll
            for (int i = 0; i < 4; i++)
#pragma unroll
                for (int j = 0; j < 4; j++) s[i][j] += ar[i] * br[j];
        }
#pragma unroll
        for (int i = 0; i < 4; i++) {
            int qi = qt * 64 + ty * 4 + i;
#pragma unroll
            for (int j = 0; j < 4; j++) {
                int kj = jt * 64 + tx * 4 + j;
                s[i][j] = (kj <= qi) ? s[i][j] * 0.125f : -1e30f;
            }
        }
        float corr[4];
#pragma unroll
        for (int i = 0; i < 4; i++) {
            float mx = fmaxf(fmaxf(s[i][0], s[i][1]), fmaxf(s[i][2], s[i][3]));
#pragma unroll
            for (int off = 8; off; off >>= 1)
                mx = fmaxf(mx, __shfl_xor_sync(0xffffffffu, mx, off));
            float mnew = fmaxf(m_i[i], mx);
            float ls = 0.f;
#pragma unroll
            for (int j = 0; j < 4; j++) {
                s[i][j] = __expf(s[i][j] - mnew);
                ls += s[i][j];
            }
#pragma unroll
            for (int off = 8; off; off >>= 1)
                ls += __shfl_xor_sync(0xffffffffu, ls, off);
            corr[i] = __expf(m_i[i] - mnew);
            l_i[i] = l_i[i] * corr[i] + ls;
            m_i[i] = mnew;
        }
        __syncthreads();
#pragma unroll
        for (int i = 0; i < 4; i++)
#pragma unroll
            for (int j = 0; j < 4; j++)
                Ks[(ty * 4 + i) * 65 + tx * 4 + j] = s[i][j];
        __syncthreads();
#pragma unroll
        for (int i = 0; i < 4; i++)
#pragma unroll
            for (int j = 0; j < 4; j++) oacc[i][j] *= corr[i];
        for (int kk = 0; kk < 64; kk++) {
            float ar[4], br[4];
#pragma unroll
            for (int i = 0; i < 4; i++) ar[i] = Ks[(ty * 4 + i) * 65 + kk];
#pragma unroll
            for (int j = 0; j < 4; j++) br[j] = Vs[kk * 64 + tx * 4 + j];
#pragma unroll
            for (int i = 0; i < 4; i++)
#pragma unroll
                for (int j = 0; j < 4; j++) oacc[i][j] += ar[i] * br[j];
        }
    }

#pragma unroll
    for (int i = 0; i < 4; i++) {
        float inv = 1.f / l_i[i];
        size_t rbase = (size_t)(rb + qt * 64 + ty * 4 + i) * DM + colbase + tx * 4;
#pragma unroll
        for (int j = 0; j < 4; j++) o[rbase + j] = oacc[i][j] * inv;
    }
}

// ---------------------------------------------------------------------------
// Loss: per-row -logp[target], then deterministic mean
// ---------------------------------------------------------------------------
__global__ __launch_bounds__(256) void loss_row_kernel(const float* __restrict__ logits,
                                                       const int* __restrict__ targets) {
    int row = blockIdx.x, tid = threadIdx.x;
    const float* lr = logits + (size_t)row * VV;
    float mx = -1e30f;
    for (int c = tid; c < VV; c += 256) mx = fmaxf(mx, lr[c]);
    mx = blockReduceMax(mx);
    float s = 0.f;
    for (int c = tid; c < VV; c += 256) s += __expf(lr[c] - mx);
    s = blockReduceSum(s);
    if (tid == 0)
        g_rowloss[row] = (mx + logf(s)) - lr[targets[row]];
}

__global__ __launch_bounds__(256) void loss_final_kernel(float* __restrict__ out) {
    float s = 0.f;
    for (int i = threadIdx.x; i < NP; i += 256) s += g_rowloss[i];
    s = blockReduceSum(s);
    if (threadIdx.x == 0) out[0] = s * (1.f / NP);
}

// ---------------------------------------------------------------------------
// Host launcher
// ---------------------------------------------------------------------------
extern "C" void kernel_launch(void* const* d_in, const int* in_sizes, int n_in,
                              void* d_out, int out_size) {
    const int*   idx  = (const int*)d_in[0];
    const int*   ibx  = (const int*)d_in[1];
    const int*   tgt  = (const int*)d_in[2];
    const float* tok  = (const float*)d_in[3];
    const float* pos  = (const float*)d_in[4];
    const float* book = (const float*)d_in[5];
    const float* Wq   = (const float*)d_in[6];
    const float* Wk   = (const float*)d_in[7];
    const float* Wv   = (const float*)d_in[8];
    const float* Wo   = (const float*)d_in[9];
    const float* bo   = (const float*)d_in[10];
    const float* ln1s = (const float*)d_in[11];
    const float* ln1b = (const float*)d_in[12];
    const float* ln2s = (const float*)d_in[13];
    const float* ln2b = (const float*)d_in[14];
    const float* W1   = (const float*)d_in[15];
    const float* b1   = (const float*)d_in[16];
    const float* W2   = (const float*)d_in[17];
    const float* b2   = (const float*)d_in[18];
    const float* lnfs = (const float*)d_in[19];
    const float* lnfb = (const float*)d_in[20];
    const float* Wh   = (const float*)d_in[21];
    const float* bh   = (const float*)d_in[22];
    float* out = (float*)d_out;

    float *x, *h, *q, *k, *v, *ao, *h2, *ff;
    cudaGetSymbolAddress((void**)&x,  g_x);
    cudaGetSymbolAddress((void**)&h,  g_h);
    cudaGetSymbolAddress((void**)&q,  g_q);
    cudaGetSymbolAddress((void**)&k,  g_k);
    cudaGetSymbolAddress((void**)&v,  g_v);
    cudaGetSymbolAddress((void**)&ao, g_ao);
    cudaGetSymbolAddress((void**)&h2, g_h2);
    cudaGetSymbolAddress((void**)&ff, g_ff);

    cudaFuncSetAttribute(attn_kernel, cudaFuncAttributeMaxDynamicSharedMemorySize,
                         ATTN_SMEM);

    embed_kernel<<<NP * DM / 256, 256>>>(idx, tok, pos);
    book_kernel<<<NP * DBK / 256, 256>>>(ibx, book);

    dim3 gDD(DM / 128, NP / 128);
    for (int l = 0; l < LL; l++) {
        ln_kernel<<<NP, 256>>>(x, ln1s + l * DM, ln1b + l * DM, h, DM);
        tgemm_kernel<<<gDD, 256>>>(h, Wq + (size_t)l * DM * DM, nullptr, nullptr, q,
                                   NP, DM, DM, 0);
        tgemm_kernel<<<gDD, 256>>>(h, Wk + (size_t)l * DM * DM, nullptr, nullptr, k,
                                   NP, DM, DM, 0);
        tgemm_kernel<<<gDD, 256>>>(h, Wv + (size_t)l * DM * DM, nullptr, nullptr, v,
                                   NP, DM, DM, 0);
        attn_kernel<<<dim3(TT / 64, HH, BB), 256, ATTN_SMEM>>>(q, k, v, ao);
        tgemm_kernel<<<gDD, 256>>>(ao, Wo + (size_t)l * DM * DM, bo + l * DM, x, x,
                                   NP, DM, DM, 0);
        ln_kernel<<<NP, 256>>>(x, ln2s + l * DM, ln2b + l * DM, h2, DIN);
        tgemm_kernel<<<dim3(DFF / 128, NP / 128), 256>>>(
            h2, W1 + (size_t)l * DIN * DFF, b1 + l * DFF, nullptr, ff,
            NP, DFF, DIN, 1);
        tgemm_kernel<<<gDD, 256>>>(ff, W2 + (size_t)l * DFF * DM, b2 + l * DM, x, x,
                                   NP, DM, DFF, 0);
    }

    ln_kernel<<<NP, 256>>>(x, lnfs, lnfb, h, DM);
    tgemm_kernel<<<dim3(VV / 128, NP / 128), 256>>>(h, Wh, bh, nullptr, out,
                                                    NP, VV, DM, 0);
    loss_row_kernel<<<NP, 256>>>(out, tgt);
    if (out_size > NP * VV)
        loss_final_kernel<<<1, 256>>>(out + (size_t)NP * VV);
}

// round 5
// speedup vs baseline: 3.8302x; 1.4270x over previous
#include <cuda_runtime.h>
#include <math.h>
#include <stdint.h>

// ---------------------------------------------------------------------------
// Model dims
// ---------------------------------------------------------------------------
#define NP   4096
#define BB   4
#define TT   1024
#define DM   1024
#define HH   16
#define HS   64
#define DFF  4096
#define VV   32000
#define LL   6
#define DBK  64
#define DIN  1088
#define QKVN 3072

// Weight arena offsets (elements)
#define OFF_QKV 0ull
#define OFF_WO  18874368ull
#define OFF_W1  25165824ull
#define OFF_W2  51904512ull
#define OFF_WH  77070336ull
#define WT_TOTAL 109838336ull

// ---------------------------------------------------------------------------
// Scratch
// ---------------------------------------------------------------------------
__device__ __align__(128) float g_x  [NP * DM];
__device__ __align__(128) float g_h  [NP * DM];     // ln out (tf32-rounded)
__device__ __align__(128) float g_qkv[NP * QKVN];
__device__ __align__(128) float g_ao [NP * DM];     // attn out (tf32-rounded)
__device__ __align__(128) float g_h2 [NP * DIN];    // ln2|book (tf32-rounded)
__device__ __align__(128) float g_ff [NP * DFF];    // relu out (tf32-rounded)
__device__ __align__(128) float g_wt [WT_TOTAL];    // transposed weights (rounded)
__device__ float g_rowloss[NP];

// ---------------------------------------------------------------------------
// Helpers
// ---------------------------------------------------------------------------
__device__ __forceinline__ uint32_t smem_u32(const void* p) {
    uint32_t a;
    asm("{ .reg .u64 t; cvta.to.shared.u64 t, %1; cvt.u32.u64 %0, t; }"
        : "=r"(a) : "l"(p));
    return a;
}

__device__ __forceinline__ float rtf32(float x) {
    uint32_t u;
    asm("cvt.rna.tf32.f32 %0, %1;" : "=r"(u) : "f"(x));
    return __uint_as_float(u);
}

__device__ __forceinline__ void cp16(uint32_t dst, const void* src) {
    asm volatile("cp.async.cg.shared.global [%0], [%1], 16;" ::"r"(dst), "l"(src));
}

#define LDSM4(r, a)                                                            \
    asm volatile("ldmatrix.sync.aligned.m8n8.x4.shared.b16 {%0,%1,%2,%3}, [%4];" \
                 : "=r"((r)[0]), "=r"((r)[1]), "=r"((r)[2]), "=r"((r)[3])      \
                 : "r"(a))

#define MMA_TF32(d, a, b)                                                      \
    asm volatile(                                                              \
        "mma.sync.aligned.m16n8k8.row.col.f32.tf32.tf32.f32 "                  \
        "{%0,%1,%2,%3}, {%4,%5,%6,%7}, {%8,%9}, {%0,%1,%2,%3};\n"              \
        : "+f"(d[0]), "+f"(d[1]), "+f"(d[2]), "+f"(d[3])                       \
        : "r"(a[0]), "r"(a[1]), "r"(a[2]), "r"(a[3]), "r"(b[0]), "r"(b[1]))

__device__ __forceinline__ float blockReduceSum(float v) {
    __shared__ float sm[33];
    int lane = threadIdx.x & 31, w = threadIdx.x >> 5;
#pragma unroll
    for (int o = 16; o; o >>= 1) v += __shfl_xor_sync(0xffffffffu, v, o);
    if (lane == 0) sm[w] = v;
    __syncthreads();
    if (w == 0) {
        v = (lane < (blockDim.x >> 5)) ? sm[lane] : 0.f;
#pragma unroll
        for (int o = 16; o; o >>= 1) v += __shfl_xor_sync(0xffffffffu, v, o);
        if (lane == 0) sm[32] = v;
    }
    __syncthreads();
    return sm[32];
}
__device__ __forceinline__ float blockReduceMax(float v) {
    __shared__ float sm[33];
    int lane = threadIdx.x & 31, w = threadIdx.x >> 5;
#pragma unroll
    for (int o = 16; o; o >>= 1) v = fmaxf(v, __shfl_xor_sync(0xffffffffu, v, o));
    if (lane == 0) sm[w] = v;
    __syncthreads();
    if (w == 0) {
        v = (lane < (blockDim.x >> 5)) ? sm[lane] : -1e30f;
#pragma unroll
        for (int o = 16; o; o >>= 1) v = fmaxf(v, __shfl_xor_sync(0xffffffffu, v, o));
        if (lane == 0) sm[32] = v;
    }
    __syncthreads();
    return sm[32];
}

// ---------------------------------------------------------------------------
// Elementwise kernels
// ---------------------------------------------------------------------------
__global__ void embed_kernel(const int* __restrict__ idx,
                             const float* __restrict__ tok,
                             const float* __restrict__ pos) {
    int gid = blockIdx.x * 256 + threadIdx.x;
    int n = gid >> 10, d = gid & 1023;
    int t = n & (TT - 1);
    g_x[gid] = tok[(size_t)idx[n] * DM + d] + pos[t * DM + d];
}

__global__ void book_kernel(const int* __restrict__ ibx,
                            const float* __restrict__ book) {
    int gid = blockIdx.x * 256 + threadIdx.x;   // NP*DBK
    int n = gid >> 6, d = gid & 63, b = n >> 10;
    g_h2[(size_t)n * DIN + DM + d] = rtf32(book[ibx[b] * DBK + d]);
}

// LayerNorm -> tf32-rounded fp32
__global__ __launch_bounds__(256) void ln_kernel(
    const float* __restrict__ x, const float* __restrict__ sc,
    const float* __restrict__ bi, float* __restrict__ y, int ldo) {
    int row = blockIdx.x, tid = threadIdx.x;
    float4 v = ((const float4*)(x + (size_t)row * DM))[tid];
    float sum = blockReduceSum(v.x + v.y + v.z + v.w);
    float mu = sum * (1.f / DM);
    float dx = v.x - mu, dy = v.y - mu, dz = v.z - mu, dw = v.w - mu;
    float sq = blockReduceSum(dx * dx + dy * dy + dz * dz + dw * dw);
    float rstd = rsqrtf(sq * (1.f / DM) + 1e-5f);
    int c = tid * 4;
    const float4 s4 = ((const float4*)sc)[tid];
    const float4 b4 = ((const float4*)bi)[tid];
    float4 o;
    o.x = rtf32(dx * rstd * s4.x + b4.x);
    o.y = rtf32(dy * rstd * s4.y + b4.y);
    o.z = rtf32(dz * rstd * s4.z + b4.z);
    o.w = rtf32(dw * rstd * s4.w + b4.w);
    *(float4*)(y + (size_t)row * ldo + c) = o;
}

// Weight transpose + tf32 round: W[K][N] -> Wt[N][K]
__global__ __launch_bounds__(256) void wtr_kernel(
    const float* __restrict__ W, float* __restrict__ Wt, int K, int N) {
    __shared__ float t[32][33];
    int n0 = blockIdx.x * 32, k0 = blockIdx.y * 32;
    int tx = threadIdx.x & 31, ty = threadIdx.x >> 5;
#pragma unroll
    for (int i = 0; i < 4; i++)
        t[ty + i * 8][tx] = W[(size_t)(k0 + ty + i * 8) * N + n0 + tx];
    __syncthreads();
#pragma unroll
    for (int i = 0; i < 4; i++) {
        int n = ty + i * 8;
        Wt[(size_t)(n0 + n) * K + k0 + tx] = rtf32(t[tx][n]);
    }
}

// ---------------------------------------------------------------------------
// tf32 mma.sync GEMM with ldmatrix fragment loads.
// C[M,N] = A[M,K] @ Bt[N,K]^T (+bias)(+relu)(+res)(round)
// A,Bt fp32 (tf32-rounded), K-contiguous. 128x128 tile, BK=32,
// 3-stage cp.async pipeline, 256 threads (8 warps, 32x64 warp tiles).
// smem row = 32 floats = 128B = 8x16B units, swizzle: unit ^= (row&7).
// ---------------------------------------------------------------------------
#define STG 32768
#define GEMM_SMEM (3 * STG)

__global__ __launch_bounds__(256, 2) void hgemm(
    const float* __restrict__ A, const float* __restrict__ Bt,
    const float* __restrict__ bias, const float* __restrict__ res,
    float* __restrict__ C, int M, int N, int K, int relu, int rnd) {
    extern __shared__ __align__(1024) char smem[];
    const uint32_t sb = smem_u32(smem);
    const int tid = threadIdx.x, lane = tid & 31, wid = tid >> 5;
    const int m0 = blockIdx.y * 128, n0 = blockIdx.x * 128;
    const int wm = (wid >> 1) * 32, wn = (wid & 1) * 64;

    // loader mapping: row = tid>>3 (0..31, +32*i), u = tid&7 (16B unit)
    const int lrow = tid >> 3, lu = tid & 7;
    const float* srcA = A + (size_t)(m0 + lrow) * K + lu * 4;
    const float* srcB = Bt + (size_t)(n0 + lrow) * K + lu * 4;
    const uint32_t d0 = (uint32_t)lrow * 128 + (((uint32_t)(lu ^ (lrow & 7))) << 4);

    // ldmatrix per-lane constants
    const uint32_t asel = lane >> 4;           // A: +1 unit for lanes 16-31
    const uint32_t bsel = (lane >> 3) & 1;     // B: +1 unit for lanes 8-15,24-31
    const uint32_t swz = lane & 7;
    const uint32_t a_ro = (uint32_t)(wm + (lane & 7) + ((lane >> 3) & 1) * 8) * 128;
    const uint32_t b_ro = (uint32_t)(wn + (lane & 7) + (lane >> 4) * 8) * 128;

    float acc[2][8][4];
#pragma unroll
    for (int i = 0; i < 2; i++)
#pragma unroll
        for (int j = 0; j < 8; j++)
#pragma unroll
            for (int c = 0; c < 4; c++) acc[i][j][c] = 0.f;

    const int KT = K >> 5;

#define LOADC(s, kof)                                                          \
    do {                                                                       \
        uint32_t bA = sb + (uint32_t)(s) * STG;                                \
        uint32_t bB = bA + 16384;                                              \
        const float* pa = srcA + (kof);                                        \
        const float* pb = srcB + (kof);                                        \
        _Pragma("unroll") for (int ii = 0; ii < 4; ii++)                       \
            cp16(bA + d0 + ii * 4096, pa + (size_t)ii * 32 * K);               \
        _Pragma("unroll") for (int ii = 0; ii < 4; ii++)                       \
            cp16(bB + d0 + ii * 4096, pb + (size_t)ii * 32 * K);               \
        asm volatile("cp.async.commit_group;" ::: "memory");                   \
    } while (0)

    LOADC(0, 0);
    LOADC(1, 32);

    int stage = 0;
    for (int i = 0; i < KT; i++) {
        if (i < KT - 1)
            asm volatile("cp.async.wait_group 1;" ::: "memory");
        else
            asm volatile("cp.async.wait_group 0;" ::: "memory");
        __syncthreads();
        if (i + 2 < KT) {
            int ns = stage + 2;
            if (ns >= 3) ns -= 3;
            LOADC(ns, (size_t)(i + 2) * 32);
        }
        const uint32_t sA = sb + (uint32_t)stage * STG;
        const uint32_t sB = sA + 16384;
#pragma unroll
        for (int ks = 0; ks < 4; ks++) {
            const uint32_t va = ((2u * ks + asel) ^ swz) << 4;
            const uint32_t vb = ((2u * ks + bsel) ^ swz) << 4;
            uint32_t af[2][4];
            LDSM4(af[0], sA + a_ro + va);
            LDSM4(af[1], sA + a_ro + 2048 + va);
            uint32_t bf[8][2];
#pragma unroll
            for (int nb = 0; nb < 4; nb++) {
                uint32_t r[4];
                LDSM4(r, sB + b_ro + nb * 2048 + vb);
                bf[2 * nb][0] = r[0]; bf[2 * nb][1] = r[1];
                bf[2 * nb + 1][0] = r[2]; bf[2 * nb + 1][1] = r[3];
            }
#pragma unroll
            for (int ii = 0; ii < 2; ii++)
#pragma unroll
                for (int j = 0; j < 8; j++) MMA_TF32(acc[ii][j], af[ii], bf[j]);
        }
        stage++;
        if (stage == 3) stage = 0;
    }

    // ---- epilogue ----
#pragma unroll
    for (int i = 0; i < 2; i++) {
        int r0 = m0 + wm + i * 16 + (lane >> 2);
#pragma unroll
        for (int j = 0; j < 8; j++) {
            int c0 = n0 + wn + j * 8 + (lane & 3) * 2;
            float v0 = acc[i][j][0], v1 = acc[i][j][1];
            float v2 = acc[i][j][2], v3 = acc[i][j][3];
            if (bias) {
                float b0 = bias[c0], b1 = bias[c0 + 1];
                v0 += b0; v1 += b1; v2 += b0; v3 += b1;
            }
            if (relu) {
                v0 = fmaxf(v0, 0.f); v1 = fmaxf(v1, 0.f);
                v2 = fmaxf(v2, 0.f); v3 = fmaxf(v3, 0.f);
            }
            size_t o0 = (size_t)r0 * N + c0;
            size_t o1 = (size_t)(r0 + 8) * N + c0;
            if (res) {
                v0 += res[o0]; v1 += res[o0 + 1];
                v2 += res[o1]; v3 += res[o1 + 1];
            }
            if (rnd) {
                v0 = rtf32(v0); v1 = rtf32(v1);
                v2 = rtf32(v2); v3 = rtf32(v3);
            }
            C[o0] = v0; C[o0 + 1] = v1;
            C[o1] = v2; C[o1 + 1] = v3;
        }
    }
#undef LOADC
}

// ---------------------------------------------------------------------------
// Flash attention (fp32 SIMT), q/k/v from fused buffer (stride QKVN),
// output tf32-rounded into g_ao (stride DM).
// ---------------------------------------------------------------------------
#define ATTN_SMEM ((2 * 64 * 65 + 64 * 64) * 4)

__global__ __launch_bounds__(256) void attn_kernel(const float* __restrict__ qkv) {
    extern __shared__ float sm[];
    float* Qs = sm;
    float* Ks = sm + 64 * 65;
    float* Vs = sm + 2 * 64 * 65;

    const float* q = qkv;
    const float* k = qkv + 1024;
    const float* v = qkv + 2048;

    int qt = blockIdx.x, h = blockIdx.y, b = blockIdx.z;
    int tid = threadIdx.x, tx = tid & 15, ty = tid >> 4;
    int rb = b * TT;
    int colbase = h * HS;

#pragma unroll
    for (int it = 0; it < 4; it++) {
        int lin = it * 1024 + tid * 4;
        int r = lin >> 6, c = lin & 63;
        float4 t4 = *(const float4*)(q + (size_t)(rb + qt * 64 + r) * QKVN + colbase + c);
        Qs[r * 65 + c + 0] = t4.x; Qs[r * 65 + c + 1] = t4.y;
        Qs[r * 65 + c + 2] = t4.z; Qs[r * 65 + c + 3] = t4.w;
    }

    float m_i[4], l_i[4], oacc[4][4];
#pragma unroll
    for (int i = 0; i < 4; i++) {
        m_i[i] = -1e30f; l_i[i] = 0.f;
#pragma unroll
        for (int j = 0; j < 4; j++) oacc[i][j] = 0.f;
    }

    for (int jt = 0; jt <= qt; jt++) {
        __syncthreads();
#pragma unroll
        for (int it = 0; it < 4; it++) {
            int lin = it * 1024 + tid * 4;
            int r = lin >> 6, c = lin & 63;
            size_t goff = (size_t)(rb + jt * 64 + r) * QKVN + colbase + c;
            float4 k4 = *(const float4*)(k + goff);
            Ks[r * 65 + c + 0] = k4.x; Ks[r * 65 + c + 1] = k4.y;
            Ks[r * 65 + c + 2] = k4.z; Ks[r * 65 + c + 3] = k4.w;
            float4 v4 = *(const float4*)(v + goff);
            *(float4*)&Vs[r * 64 + c] = v4;
        }
        __syncthreads();

        float s[4][4];
#pragma unroll
        for (int i = 0; i < 4; i++)
#pragma unroll
            for (int j = 0; j < 4; j++) s[i][j] = 0.f;
        for (int d = 0; d < 64; d++) {
            float ar[4], br[4];
#pragma unroll
            for (int i = 0; i < 4; i++) ar[i] = Qs[(ty * 4 + i) * 65 + d];
#pragma unroll
            for (int j = 0; j < 4; j++) br[j] = Ks[(tx * 4 + j) * 65 + d];
#pragma unroll
            for (int i = 0; i < 4; i++)
#pragma unroll
                for (int j = 0; j < 4; j++) s[i][j] += ar[i] * br[j];
        }
#pragma unroll
        for (int i = 0; i < 4; i++) {
            int qi = qt * 64 + ty * 4 + i;
#pragma unroll
            for (int j = 0; j < 4; j++) {
                int kj = jt * 64 + tx * 4 + j;
                s[i][j] = (kj <= qi) ? s[i][j] * 0.125f : -1e30f;
            }
        }
        float corr[4];
#pragma unroll
        for (int i = 0; i < 4; i++) {
            float mx = fmaxf(fmaxf(s[i][0], s[i][1]), fmaxf(s[i][2], s[i][3]));
#pragma unroll
            for (int off = 8; off; off >>= 1)
                mx = fmaxf(mx, __shfl_xor_sync(0xffffffffu, mx, off));
            float mnew = fmaxf(m_i[i], mx);
            float ls = 0.f;
#pragma unroll
            for (int j = 0; j < 4; j++) {
                s[i][j] = __expf(s[i][j] - mnew);
                ls += s[i][j];
            }
#pragma unroll
            for (int off = 8; off; off >>= 1)
                ls += __shfl_xor_sync(0xffffffffu, ls, off);
            corr[i] = __expf(m_i[i] - mnew);
            l_i[i] = l_i[i] * corr[i] + ls;
            m_i[i] = mnew;
        }
        __syncthreads();
#pragma unroll
        for (int i = 0; i < 4; i++)
#pragma unroll
            for (int j = 0; j < 4; j++)
                Ks[(ty * 4 + i) * 65 + tx * 4 + j] = s[i][j];
        __syncthreads();
#pragma unroll
        for (int i = 0; i < 4; i++)
#pragma unroll
            for (int j = 0; j < 4; j++) oacc[i][j] *= corr[i];
        for (int kk = 0; kk < 64; kk++) {
            float ar[4], br[4];
#pragma unroll
            for (int i = 0; i < 4; i++) ar[i] = Ks[(ty * 4 + i) * 65 + kk];
#pragma unroll
            for (int j = 0; j < 4; j++) br[j] = Vs[kk * 64 + tx * 4 + j];
#pragma unroll
            for (int i = 0; i < 4; i++)
#pragma unroll
                for (int j = 0; j < 4; j++) oacc[i][j] += ar[i] * br[j];
        }
    }

#pragma unroll
    for (int i = 0; i < 4; i++) {
        float inv = 1.f / l_i[i];
        size_t rbase = (size_t)(rb + qt * 64 + ty * 4 + i) * DM + colbase + tx * 4;
        float4 o;
        o.x = rtf32(oacc[i][0] * inv);
        o.y = rtf32(oacc[i][1] * inv);
        o.z = rtf32(oacc[i][2] * inv);
        o.w = rtf32(oacc[i][3] * inv);
        *(float4*)&g_ao[rbase] = o;
    }
}

// ---------------------------------------------------------------------------
// Loss
// ---------------------------------------------------------------------------
__global__ __launch_bounds__(256) void loss_row_kernel(const float* __restrict__ logits,
                                                       const int* __restrict__ targets) {
    int row = blockIdx.x, tid = threadIdx.x;
    const float* lr = logits + (size_t)row * VV;
    float mx = -1e30f;
    for (int c = tid; c < VV; c += 256) mx = fmaxf(mx, lr[c]);
    mx = blockReduceMax(mx);
    float s = 0.f;
    for (int c = tid; c < VV; c += 256) s += __expf(lr[c] - mx);
    s = blockReduceSum(s);
    if (tid == 0) g_rowloss[row] = (mx + logf(s)) - lr[targets[row]];
}

__global__ __launch_bounds__(256) void loss_final_kernel(float* __restrict__ out) {
    float s = 0.f;
    for (int i = threadIdx.x; i < NP; i += 256) s += g_rowloss[i];
    s = blockReduceSum(s);
    if (threadIdx.x == 0) out[0] = s * (1.f / NP);
}

// ---------------------------------------------------------------------------
// Host launcher
// ---------------------------------------------------------------------------
extern "C" void kernel_launch(void* const* d_in, const int* in_sizes, int n_in,
                              void* d_out, int out_size) {
    const int*   idx  = (const int*)d_in[0];
    const int*   ibx  = (const int*)d_in[1];
    const int*   tgt  = (const int*)d_in[2];
    const float* tok  = (const float*)d_in[3];
    const float* pos  = (const float*)d_in[4];
    const float* book = (const float*)d_in[5];
    const float* Wq   = (const float*)d_in[6];
    const float* Wk   = (const float*)d_in[7];
    const float* Wv   = (const float*)d_in[8];
    const float* Wo   = (const float*)d_in[9];
    const float* bo   = (const float*)d_in[10];
    const float* ln1s = (const float*)d_in[11];
    const float* ln1b = (const float*)d_in[12];
    const float* ln2s = (const float*)d_in[13];
    const float* ln2b = (const float*)d_in[14];
    const float* W1   = (const float*)d_in[15];
    const float* b1   = (const float*)d_in[16];
    const float* W2   = (const float*)d_in[17];
    const float* b2   = (const float*)d_in[18];
    const float* lnfs = (const float*)d_in[19];
    const float* lnfb = (const float*)d_in[20];
    const float* Wh   = (const float*)d_in[21];
    const float* bh   = (const float*)d_in[22];
    float* out = (float*)d_out;

    float *x, *h, *qkv, *ao, *h2, *ff, *wt;
    cudaGetSymbolAddress((void**)&x,   g_x);
    cudaGetSymbolAddress((void**)&h,   g_h);
    cudaGetSymbolAddress((void**)&qkv, g_qkv);
    cudaGetSymbolAddress((void**)&ao,  g_ao);
    cudaGetSymbolAddress((void**)&h2,  g_h2);
    cudaGetSymbolAddress((void**)&ff,  g_ff);
    cudaGetSymbolAddress((void**)&wt,  g_wt);

    cudaFuncSetAttribute(attn_kernel, cudaFuncAttributeMaxDynamicSharedMemorySize,
                         ATTN_SMEM);
    cudaFuncSetAttribute(hgemm, cudaFuncAttributeMaxDynamicSharedMemorySize,
                         GEMM_SMEM);

    // ---- weight transpose + tf32 round ----
    for (int l = 0; l < LL; l++) {
        size_t qb = OFF_QKV + (size_t)l * 3 * DM * DM;
        wtr_kernel<<<dim3(DM / 32, DM / 32), 256>>>(Wq + (size_t)l * DM * DM,
                                                    wt + qb, DM, DM);
        wtr_kernel<<<dim3(DM / 32, DM / 32), 256>>>(Wk + (size_t)l * DM * DM,
                                                    wt + qb + (size_t)DM * DM, DM, DM);
        wtr_kernel<<<dim3(DM / 32, DM / 32), 256>>>(Wv + (size_t)l * DM * DM,
                                                    wt + qb + 2ull * DM * DM, DM, DM);
        wtr_kernel<<<dim3(DM / 32, DM / 32), 256>>>(Wo + (size_t)l * DM * DM,
                                                    wt + OFF_WO + (size_t)l * DM * DM,
                                                    DM, DM);
        wtr_kernel<<<dim3(DFF / 32, DIN / 32), 256>>>(
            W1 + (size_t)l * DIN * DFF, wt + OFF_W1 + (size_t)l * DFF * DIN, DIN, DFF);
        wtr_kernel<<<dim3(DM / 32, DFF / 32), 256>>>(
            W2 + (size_t)l * DFF * DM, wt + OFF_W2 + (size_t)l * DM * DFF, DFF, DM);
    }
    wtr_kernel<<<dim3(VV / 32, DM / 32), 256>>>(Wh, wt + OFF_WH, DM, VV);

    embed_kernel<<<NP * DM / 256, 256>>>(idx, tok, pos);
    book_kernel<<<NP * DBK / 256, 256>>>(ibx, book);

    for (int l = 0; l < LL; l++) {
        ln_kernel<<<NP, 256>>>(x, ln1s + l * DM, ln1b + l * DM, h, DM);
        hgemm<<<dim3(QKVN / 128, NP / 128), 256, GEMM_SMEM>>>(
            h, wt + OFF_QKV + (size_t)l * 3 * DM * DM, nullptr, nullptr, qkv,
            NP, QKVN, DM, 0, 0);
        attn_kernel<<<dim3(TT / 64, HH, BB), 256, ATTN_SMEM>>>(qkv);
        hgemm<<<dim3(DM / 128, NP / 128), 256, GEMM_SMEM>>>(
            ao, wt + OFF_WO + (size_t)l * DM * DM, bo + l * DM, x, x,
            NP, DM, DM, 0, 0);
        ln_kernel<<<NP, 256>>>(x, ln2s + l * DM, ln2b + l * DM, h2, DIN);
        hgemm<<<dim3(DFF / 128, NP / 128), 256, GEMM_SMEM>>>(
            h2, wt + OFF_W1 + (size_t)l * DFF * DIN, b1 + l * DFF, nullptr, ff,
            NP, DFF, DIN, 1, 1);
        hgemm<<<dim3(DM / 128, NP / 128), 256, GEMM_SMEM>>>(
            ff, wt + OFF_W2 + (size_t)l * DM * DFF, b2 + l * DM, x, x,
            NP, DM, DFF, 0, 0);
    }

    ln_kernel<<<NP, 256>>>(x, lnfs, lnfb, h, DM);
    hgemm<<<dim3(VV / 128, NP / 128), 256, GEMM_SMEM>>>(
        h, wt + OFF_WH, bh, nullptr, out, NP, VV, DM, 0, 0);
    loss_row_kernel<<<NP, 256>>>(out, tgt);
    if (out_size > NP * VV)
        loss_final_kernel<<<1, 256>>>(out + (size_t)NP * VV);
}

// round 6
// speedup vs baseline: 3.8790x; 1.0128x over previous
#include <cuda_runtime.h>
#include <math.h>
#include <stdint.h>

// ---------------------------------------------------------------------------
// Model dims
// ---------------------------------------------------------------------------
#define NP   4096
#define BB   4
#define TT   1024
#define DM   1024
#define HH   16
#define HS   64
#define DFF  4096
#define LL   6
#define VV   32000
#define DBK  64
#define DIN  1088
#define QKVN 3072

// Weight arena offsets (elements)
#define OFF_QKV 0ull
#define OFF_WO  18874368ull
#define OFF_W1  25165824ull
#define OFF_W2  51904512ull
#define OFF_WH  77070336ull
#define WT_TOTAL 109838336ull

// ---------------------------------------------------------------------------
// Scratch
// ---------------------------------------------------------------------------
__device__ __align__(128) float g_x  [NP * DM];
__device__ __align__(128) float g_h  [NP * DM];
__device__ __align__(128) float g_qkv[NP * QKVN];
__device__ __align__(128) float g_ao [NP * DM];
__device__ __align__(128) float g_h2 [NP * DIN];
__device__ __align__(128) float g_ff [NP * DFF];
__device__ __align__(128) float g_wt [WT_TOTAL];
__device__ float g_rowloss[NP];

// ---------------------------------------------------------------------------
// Helpers
// ---------------------------------------------------------------------------
__device__ __forceinline__ uint32_t smem_u32(const void* p) {
    uint32_t a;
    asm("{ .reg .u64 t; cvta.to.shared.u64 t, %1; cvt.u32.u64 %0, t; }"
        : "=r"(a) : "l"(p));
    return a;
}

__device__ __forceinline__ float rtf32(float x) {
    uint32_t u;
    asm("cvt.rna.tf32.f32 %0, %1;" : "=r"(u) : "f"(x));
    return __uint_as_float(u);
}

__device__ __forceinline__ void cp16(uint32_t dst, const void* src) {
    asm volatile("cp.async.cg.shared.global [%0], [%1], 16;" ::"r"(dst), "l"(src));
}

#define LDSM4(r, a)                                                            \
    asm volatile("ldmatrix.sync.aligned.m8n8.x4.shared.b16 {%0,%1,%2,%3}, [%4];" \
                 : "=r"((r)[0]), "=r"((r)[1]), "=r"((r)[2]), "=r"((r)[3])      \
                 : "r"(a))

#define MMA_TF32(d, a, b)                                                      \
    asm volatile(                                                              \
        "mma.sync.aligned.m16n8k8.row.col.f32.tf32.tf32.f32 "                  \
        "{%0,%1,%2,%3}, {%4,%5,%6,%7}, {%8,%9}, {%0,%1,%2,%3};\n"              \
        : "+f"(d[0]), "+f"(d[1]), "+f"(d[2]), "+f"(d[3])                       \
        : "r"(a[0]), "r"(a[1]), "r"(a[2]), "r"(a[3]), "r"(b[0]), "r"(b[1]))

__device__ __forceinline__ float warpSum(float v) {
#pragma unroll
    for (int o = 16; o; o >>= 1) v += __shfl_xor_sync(0xffffffffu, v, o);
    return v;
}
__device__ __forceinline__ float warpMax(float v) {
#pragma unroll
    for (int o = 16; o; o >>= 1) v = fmaxf(v, __shfl_xor_sync(0xffffffffu, v, o));
    return v;
}

__device__ __forceinline__ float blockReduceSum(float v) {
    __shared__ float sm[33];
    int lane = threadIdx.x & 31, w = threadIdx.x >> 5;
    v = warpSum(v);
    if (lane == 0) sm[w] = v;
    __syncthreads();
    if (w == 0) {
        v = (lane < (blockDim.x >> 5)) ? sm[lane] : 0.f;
        v = warpSum(v);
        if (lane == 0) sm[32] = v;
    }
    __syncthreads();
    return sm[32];
}
__device__ __forceinline__ float blockReduceMax(float v) {
    __shared__ float sm[33];
    int lane = threadIdx.x & 31, w = threadIdx.x >> 5;
    v = warpMax(v);
    if (lane == 0) sm[w] = v;
    __syncthreads();
    if (w == 0) {
        v = (lane < (blockDim.x >> 5)) ? sm[lane] : -1e30f;
        v = warpMax(v);
        if (lane == 0) sm[32] = v;
    }
    __syncthreads();
    return sm[32];
}

// ---------------------------------------------------------------------------
// Elementwise kernels
// ---------------------------------------------------------------------------
__global__ void embed_kernel(const int* __restrict__ idx,
                             const float* __restrict__ tok,
                             const float* __restrict__ pos) {
    int gid = blockIdx.x * 256 + threadIdx.x;       // over NP*DM/4
    int n = gid >> 8, c4 = (gid & 255) * 4;
    int t = n & (TT - 1);
    const float4 a = *(const float4*)(tok + (size_t)idx[n] * DM + c4);
    const float4 b = *(const float4*)(pos + (size_t)t * DM + c4);
    float4 o;
    o.x = a.x + b.x; o.y = a.y + b.y; o.z = a.z + b.z; o.w = a.w + b.w;
    *(float4*)(g_x + (size_t)n * DM + c4) = o;
}

__global__ void book_kernel(const int* __restrict__ ibx,
                            const float* __restrict__ book) {
    int gid = blockIdx.x * 256 + threadIdx.x;   // NP*DBK
    int n = gid >> 6, d = gid & 63, b = n >> 10;
    g_h2[(size_t)n * DIN + DM + d] = rtf32(book[ibx[b] * DBK + d]);
}

// LayerNorm: warp per row, shfl-only reductions, float4 I/O.
__global__ __launch_bounds__(256) void ln_kernel(
    const float* __restrict__ x, const float* __restrict__ sc,
    const float* __restrict__ bi, float* __restrict__ y, int ldo) {
    int warp = threadIdx.x >> 5, lane = threadIdx.x & 31;
    int row = blockIdx.x * 8 + warp;
    const float4* xr = (const float4*)(x + (size_t)row * DM);
    float4 v[8];
    float sum = 0.f;
#pragma unroll
    for (int i = 0; i < 8; i++) {
        v[i] = xr[i * 32 + lane];
        sum += v[i].x + v[i].y + v[i].z + v[i].w;
    }
    float mu = warpSum(sum) * (1.f / DM);
    float sq = 0.f;
#pragma unroll
    for (int i = 0; i < 8; i++) {
        float dx = v[i].x - mu, dy = v[i].y - mu;
        float dz = v[i].z - mu, dw = v[i].w - mu;
        sq += dx * dx + dy * dy + dz * dz + dw * dw;
    }
    float rstd = rsqrtf(warpSum(sq) * (1.f / DM) + 1e-5f);
#pragma unroll
    for (int i = 0; i < 8; i++) {
        int c4 = i * 32 + lane;
        float4 s4 = ((const float4*)sc)[c4];
        float4 b4 = ((const float4*)bi)[c4];
        float4 o;
        o.x = rtf32((v[i].x - mu) * rstd * s4.x + b4.x);
        o.y = rtf32((v[i].y - mu) * rstd * s4.y + b4.y);
        o.z = rtf32((v[i].z - mu) * rstd * s4.z + b4.z);
        o.w = rtf32((v[i].w - mu) * rstd * s4.w + b4.w);
        *(float4*)(y + (size_t)row * ldo + c4 * 4) = o;
    }
}

// Weight transpose + tf32 round: W[K][N] -> Wt[N][K].
// 64x64 tile, float4 global loads AND stores, padded smem.
__global__ __launch_bounds__(256) void wtr_kernel(
    const float* __restrict__ W, float* __restrict__ Wt, int K, int N) {
    __shared__ float s[64][65];
    int n0 = blockIdx.x * 64, k0 = blockIdx.y * 64;
    int t = threadIdx.x;
    int kk = t >> 4, nn4 = (t & 15) * 4;
#pragma unroll
    for (int i = 0; i < 4; i++) {
        int k = kk + 16 * i;
        float4 w = *(const float4*)(W + (size_t)(k0 + k) * N + n0 + nn4);
        s[nn4 + 0][k] = w.x;
        s[nn4 + 1][k] = w.y;
        s[nn4 + 2][k] = w.z;
        s[nn4 + 3][k] = w.w;
    }
    __syncthreads();
    int k4 = (t & 15) * 4;
#pragma unroll
    for (int i = 0; i < 4; i++) {
        int n = (t >> 4) + 16 * i;
        float4 o;
        o.x = rtf32(s[n][k4 + 0]);
        o.y = rtf32(s[n][k4 + 1]);
        o.z = rtf32(s[n][k4 + 2]);
        o.w = rtf32(s[n][k4 + 3]);
        *(float4*)(Wt + (size_t)(n0 + n) * K + k0 + k4) = o;
    }
}

// ---------------------------------------------------------------------------
// tf32 mma.sync GEMM with ldmatrix fragment loads (unchanged from R5).
// ---------------------------------------------------------------------------
#define STG 32768
#define GEMM_SMEM (3 * STG)

__global__ __launch_bounds__(256, 2) void hgemm(
    const float* __restrict__ A, const float* __restrict__ Bt,
    const float* __restrict__ bias, const float* __restrict__ res,
    float* __restrict__ C, int M, int N, int K, int relu, int rnd) {
    extern __shared__ __align__(1024) char smem[];
    const uint32_t sb = smem_u32(smem);
    const int tid = threadIdx.x, lane = tid & 31, wid = tid >> 5;
    const int m0 = blockIdx.y * 128, n0 = blockIdx.x * 128;
    const int wm = (wid >> 1) * 32, wn = (wid & 1) * 64;

    const int lrow = tid >> 3, lu = tid & 7;
    const float* srcA = A + (size_t)(m0 + lrow) * K + lu * 4;
    const float* srcB = Bt + (size_t)(n0 + lrow) * K + lu * 4;
    const uint32_t d0 = (uint32_t)lrow * 128 + (((uint32_t)(lu ^ (lrow & 7))) << 4);

    const uint32_t asel = lane >> 4;
    const uint32_t bsel = (lane >> 3) & 1;
    const uint32_t swz = lane & 7;
    const uint32_t a_ro = (uint32_t)(wm + (lane & 7) + ((lane >> 3) & 1) * 8) * 128;
    const uint32_t b_ro = (uint32_t)(wn + (lane & 7) + (lane >> 4) * 8) * 128;

    float acc[2][8][4];
#pragma unroll
    for (int i = 0; i < 2; i++)
#pragma unroll
        for (int j = 0; j < 8; j++)
#pragma unroll
            for (int c = 0; c < 4; c++) acc[i][j][c] = 0.f;

    const int KT = K >> 5;

#define LOADC(s, kof)                                                          \
    do {                                                                       \
        uint32_t bA = sb + (uint32_t)(s) * STG;                                \
        uint32_t bB = bA + 16384;                                              \
        const float* pa = srcA + (kof);                                        \
        const float* pb = srcB + (kof);                                        \
        _Pragma("unroll") for (int ii = 0; ii < 4; ii++)                       \
            cp16(bA + d0 + ii * 4096, pa + (size_t)ii * 32 * K);               \
        _Pragma("unroll") for (int ii = 0; ii < 4; ii++)                       \
            cp16(bB + d0 + ii * 4096, pb + (size_t)ii * 32 * K);               \
        asm volatile("cp.async.commit_group;" ::: "memory");                   \
    } while (0)

    LOADC(0, 0);
    LOADC(1, 32);

    int stage = 0;
    for (int i = 0; i < KT; i++) {
        if (i < KT - 1)
            asm volatile("cp.async.wait_group 1;" ::: "memory");
        else
            asm volatile("cp.async.wait_group 0;" ::: "memory");
        __syncthreads();
        if (i + 2 < KT) {
            int ns = stage + 2;
            if (ns >= 3) ns -= 3;
            LOADC(ns, (size_t)(i + 2) * 32);
        }
        const uint32_t sA = sb + (uint32_t)stage * STG;
        const uint32_t sB = sA + 16384;
#pragma unroll
        for (int ks = 0; ks < 4; ks++) {
            const uint32_t va = ((2u * ks + asel) ^ swz) << 4;
            const uint32_t vb = ((2u * ks + bsel) ^ swz) << 4;
            uint32_t af[2][4];
            LDSM4(af[0], sA + a_ro + va);
            LDSM4(af[1], sA + a_ro + 2048 + va);
            uint32_t bf[8][2];
#pragma unroll
            for (int nb = 0; nb < 4; nb++) {
                uint32_t r[4];
                LDSM4(r, sB + b_ro + nb * 2048 + vb);
                bf[2 * nb][0] = r[0]; bf[2 * nb][1] = r[1];
                bf[2 * nb + 1][0] = r[2]; bf[2 * nb + 1][1] = r[3];
            }
#pragma unroll
            for (int ii = 0; ii < 2; ii++)
#pragma unroll
                for (int j = 0; j < 8; j++) MMA_TF32(acc[ii][j], af[ii], bf[j]);
        }
        stage++;
        if (stage == 3) stage = 0;
    }

#pragma unroll
    for (int i = 0; i < 2; i++) {
        int r0 = m0 + wm + i * 16 + (lane >> 2);
#pragma unroll
        for (int j = 0; j < 8; j++) {
            int c0 = n0 + wn + j * 8 + (lane & 3) * 2;
            float v0 = acc[i][j][0], v1 = acc[i][j][1];
            float v2 = acc[i][j][2], v3 = acc[i][j][3];
            if (bias) {
                float b0 = bias[c0], b1 = bias[c0 + 1];
                v0 += b0; v1 += b1; v2 += b0; v3 += b1;
            }
            if (relu) {
                v0 = fmaxf(v0, 0.f); v1 = fmaxf(v1, 0.f);
                v2 = fmaxf(v2, 0.f); v3 = fmaxf(v3, 0.f);
            }
            size_t o0 = (size_t)r0 * N + c0;
            size_t o1 = (size_t)(r0 + 8) * N + c0;
            if (res) {
                v0 += res[o0]; v1 += res[o0 + 1];
                v2 += res[o1]; v3 += res[o1 + 1];
            }
            if (rnd) {
                v0 = rtf32(v0); v1 = rtf32(v1);
                v2 = rtf32(v2); v3 = rtf32(v3);
            }
            C[o0] = v0; C[o0 + 1] = v1;
            C[o1] = v2; C[o1 + 1] = v3;
        }
    }
#undef LOADC
}

// ---------------------------------------------------------------------------
// Flash attention (fp32 SIMT), q/k/v from fused buffer (stride QKVN),
// output tf32-rounded into g_ao (stride DM).
// ---------------------------------------------------------------------------
#define ATTN_SMEM ((2 * 64 * 65 + 64 * 64) * 4)

__global__ __launch_bounds__(256) void attn_kernel(const float* __restrict__ qkv) {
    extern __shared__ float sm[];
    float* Qs = sm;
    float* Ks = sm + 64 * 65;
    float* Vs = sm + 2 * 64 * 65;

    const float* q = qkv;
    const float* k = qkv + 1024;
    const float* v = qkv + 2048;

    int qt = blockIdx.x, h = blockIdx.y, b = blockIdx.z;
    int tid = threadIdx.x, tx = tid & 15, ty = tid >> 4;
    int rb = b * TT;
    int colbase = h * HS;

#pragma unroll
    for (int it = 0; it < 4; it++) {
        int lin = it * 1024 + tid * 4;
        int r = lin >> 6, c = lin & 63;
        float4 t4 = *(const float4*)(q + (size_t)(rb + qt * 64 + r) * QKVN + colbase + c);
        Qs[r * 65 + c + 0] = t4.x; Qs[r * 65 + c + 1] = t4.y;
        Qs[r * 65 + c + 2] = t4.z; Qs[r * 65 + c + 3] = t4.w;
    }

    float m_i[4], l_i[4], oacc[4][4];
#pragma unroll
    for (int i = 0; i < 4; i++) {
        m_i[i] = -1e30f; l_i[i] = 0.f;
#pragma unroll
        for (int j = 0; j < 4; j++) oacc[i][j] = 0.f;
    }

    for (int jt = 0; jt <= qt; jt++) {
        __syncthreads();
#pragma unroll
        for (int it = 0; it < 4; it++) {
            int lin = it * 1024 + tid * 4;
            int r = lin >> 6, c = lin & 63;
            size_t goff = (size_t)(rb + jt * 64 + r) * QKVN + colbase + c;
            float4 k4 = *(const float4*)(k + goff);
            Ks[r * 65 + c + 0] = k4.x; Ks[r * 65 + c + 1] = k4.y;
            Ks[r * 65 + c + 2] = k4.z; Ks[r * 65 + c + 3] = k4.w;
            float4 v4 = *(const float4*)(v + goff);
            *(float4*)&Vs[r * 64 + c] = v4;
        }
        __syncthreads();

        float s[4][4];
#pragma unroll
        for (int i = 0; i < 4; i++)
#pragma unroll
            for (int j = 0; j < 4; j++) s[i][j] = 0.f;
        for (int d = 0; d < 64; d++) {
            float ar[4], br[4];
#pragma unroll
            for (int i = 0; i < 4; i++) ar[i] = Qs[(ty * 4 + i) * 65 + d];
#pragma unroll
            for (int j = 0; j < 4; j++) br[j] = Ks[(tx * 4 + j) * 65 + d];
#pragma unroll
            for (int i = 0; i < 4; i++)
#pragma unroll
                for (int j = 0; j < 4; j++) s[i][j] += ar[i] * br[j];
        }
#pragma unroll
        for (int i = 0; i < 4; i++) {
            int qi = qt * 64 + ty * 4 + i;
#pragma unroll
            for (int j = 0; j < 4; j++) {
                int kj = jt * 64 + tx * 4 + j;
                s[i][j] = (kj <= qi) ? s[i][j] * 0.125f : -1e30f;
            }
        }
        float corr[4];
#pragma unroll
        for (int i = 0; i < 4; i++) {
            float mx = fmaxf(fmaxf(s[i][0], s[i][1]), fmaxf(s[i][2], s[i][3]));
#pragma unroll
            for (int off = 8; off; off >>= 1)
                mx = fmaxf(mx, __shfl_xor_sync(0xffffffffu, mx, off));
            float mnew = fmaxf(m_i[i], mx);
            float ls = 0.f;
#pragma unroll
            for (int j = 0; j < 4; j++) {
                s[i][j] = __expf(s[i][j] - mnew);
                ls += s[i][j];
            }
#pragma unroll
            for (int off = 8; off; off >>= 1)
                ls += __shfl_xor_sync(0xffffffffu, ls, off);
            corr[i] = __expf(m_i[i] - mnew);
            l_i[i] = l_i[i] * corr[i] + ls;
            m_i[i] = mnew;
        }
        __syncthreads();
#pragma unroll
        for (int i = 0; i < 4; i++)
#pragma unroll
            for (int j = 0; j < 4; j++)
                Ks[(ty * 4 + i) * 65 + tx * 4 + j] = s[i][j];
        __syncthreads();
#pragma unroll
        for (int i = 0; i < 4; i++)
#pragma unroll
            for (int j = 0; j < 4; j++) oacc[i][j] *= corr[i];
        for (int kk = 0; kk < 64; kk++) {
            float ar[4], br[4];
#pragma unroll
            for (int i = 0; i < 4; i++) ar[i] = Ks[(ty * 4 + i) * 65 + kk];
#pragma unroll
            for (int j = 0; j < 4; j++) br[j] = Vs[kk * 64 + tx * 4 + j];
#pragma unroll
            for (int i = 0; i < 4; i++)
#pragma unroll
                for (int j = 0; j < 4; j++) oacc[i][j] += ar[i] * br[j];
        }
    }

#pragma unroll
    for (int i = 0; i < 4; i++) {
        float inv = 1.f / l_i[i];
        size_t rbase = (size_t)(rb + qt * 64 + ty * 4 + i) * DM + colbase + tx * 4;
        float4 o;
        o.x = rtf32(oacc[i][0] * inv);
        o.y = rtf32(oacc[i][1] * inv);
        o.z = rtf32(oacc[i][2] * inv);
        o.w = rtf32(oacc[i][3] * inv);
        *(float4*)&g_ao[rbase] = o;
    }
}

// ---------------------------------------------------------------------------
// Loss: single-pass online softmax per row, then deterministic mean
// ---------------------------------------------------------------------------
__global__ __launch_bounds__(256) void loss_row_kernel(const float* __restrict__ logits,
                                                       const int* __restrict__ targets) {
    int row = blockIdx.x, tid = threadIdx.x;
    const float* lr = logits + (size_t)row * VV;
    float m = -1e30f, s = 0.f;
    for (int c = tid; c < VV; c += 256) {
        float v = lr[c];
        float nm = fmaxf(m, v);
        s = s * __expf(m - nm) + __expf(v - nm);
        m = nm;
    }
    float M = blockReduceMax(m);
    s *= __expf(m - M);
    float S = blockReduceSum(s);
    if (tid == 0) g_rowloss[row] = (M + logf(S)) - lr[targets[row]];
}

__global__ __launch_bounds__(256) void loss_final_kernel(float* __restrict__ out) {
    float s = 0.f;
    for (int i = threadIdx.x; i < NP; i += 256) s += g_rowloss[i];
    s = blockReduceSum(s);
    if (threadIdx.x == 0) out[0] = s * (1.f / NP);
}

// ---------------------------------------------------------------------------
// Host launcher
// ---------------------------------------------------------------------------
extern "C" void kernel_launch(void* const* d_in, const int* in_sizes, int n_in,
                              void* d_out, int out_size) {
    const int*   idx  = (const int*)d_in[0];
    const int*   ibx  = (const int*)d_in[1];
    const int*   tgt  = (const int*)d_in[2];
    const float* tok  = (const float*)d_in[3];
    const float* pos  = (const float*)d_in[4];
    const float* book = (const float*)d_in[5];
    const float* Wq   = (const float*)d_in[6];
    const float* Wk   = (const float*)d_in[7];
    const float* Wv   = (const float*)d_in[8];
    const float* Wo   = (const float*)d_in[9];
    const float* bo   = (const float*)d_in[10];
    const float* ln1s = (const float*)d_in[11];
    const float* ln1b = (const float*)d_in[12];
    const float* ln2s = (const float*)d_in[13];
    const float* ln2b = (const float*)d_in[14];
    const float* W1   = (const float*)d_in[15];
    const float* b1   = (const float*)d_in[16];
    const float* W2   = (const float*)d_in[17];
    const float* b2   = (const float*)d_in[18];
    const float* lnfs = (const float*)d_in[19];
    const float* lnfb = (const float*)d_in[20];
    const float* Wh   = (const float*)d_in[21];
    const float* bh   = (const float*)d_in[22];
    float* out = (float*)d_out;

    float *x, *h, *qkv, *ao, *h2, *ff, *wt;
    cudaGetSymbolAddress((void**)&x,   g_x);
    cudaGetSymbolAddress((void**)&h,   g_h);
    cudaGetSymbolAddress((void**)&qkv, g_qkv);
    cudaGetSymbolAddress((void**)&ao,  g_ao);
    cudaGetSymbolAddress((void**)&h2,  g_h2);
    cudaGetSymbolAddress((void**)&ff,  g_ff);
    cudaGetSymbolAddress((void**)&wt,  g_wt);

    cudaFuncSetAttribute(attn_kernel, cudaFuncAttributeMaxDynamicSharedMemorySize,
                         ATTN_SMEM);
    cudaFuncSetAttribute(hgemm, cudaFuncAttributeMaxDynamicSharedMemorySize,
                         GEMM_SMEM);

    // ---- weight transpose + tf32 round ----
    for (int l = 0; l < LL; l++) {
        size_t qb = OFF_QKV + (size_t)l * 3 * DM * DM;
        wtr_kernel<<<dim3(DM / 64, DM / 64), 256>>>(Wq + (size_t)l * DM * DM,
                                                    wt + qb, DM, DM);
        wtr_kernel<<<dim3(DM / 64, DM / 64), 256>>>(Wk + (size_t)l * DM * DM,
                                                    wt + qb + (size_t)DM * DM, DM, DM);
        wtr_kernel<<<dim3(DM / 64, DM / 64), 256>>>(Wv + (size_t)l * DM * DM,
                                                    wt + qb + 2ull * DM * DM, DM, DM);
        wtr_kernel<<<dim3(DM / 64, DM / 64), 256>>>(Wo + (size_t)l * DM * DM,
                                                    wt + OFF_WO + (size_t)l * DM * DM,
                                                    DM, DM);
        wtr_kernel<<<dim3(DFF / 64, DIN / 64), 256>>>(
            W1 + (size_t)l * DIN * DFF, wt + OFF_W1 + (size_t)l * DFF * DIN, DIN, DFF);
        wtr_kernel<<<dim3(DM / 64, DFF / 64), 256>>>(
            W2 + (size_t)l * DFF * DM, wt + OFF_W2 + (size_t)l * DM * DFF, DFF, DM);
    }
    wtr_kernel<<<dim3(VV / 64, DM / 64), 256>>>(Wh, wt + OFF_WH, DM, VV);

    embed_kernel<<<NP * DM / 1024, 256>>>(idx, tok, pos);
    book_kernel<<<NP * DBK / 256, 256>>>(ibx, book);

    for (int l = 0; l < LL; l++) {
        ln_kernel<<<NP / 8, 256>>>(x, ln1s + l * DM, ln1b + l * DM, h, DM);
        hgemm<<<dim3(QKVN / 128, NP / 128), 256, GEMM_SMEM>>>(
            h, wt + OFF_QKV + (size_t)l * 3 * DM * DM, nullptr, nullptr, qkv,
            NP, QKVN, DM, 0, 0);
        attn_kernel<<<dim3(TT / 64, HH, BB), 256, ATTN_SMEM>>>(qkv);
        hgemm<<<dim3(DM / 128, NP / 128), 256, GEMM_SMEM>>>(
            ao, wt + OFF_WO + (size_t)l * DM * DM, bo + l * DM, x, x,
            NP, DM, DM, 0, 0);
        ln_kernel<<<NP / 8, 256>>>(x, ln2s + l * DM, ln2b + l * DM, h2, DIN);
        hgemm<<<dim3(DFF / 128, NP / 128), 256, GEMM_SMEM>>>(
            h2, wt + OFF_W1 + (size_t)l * DFF * DIN, b1 + l * DFF, nullptr, ff,
            NP, DFF, DIN, 1, 1);
        hgemm<<<dim3(DM / 128, NP / 128), 256, GEMM_SMEM>>>(
            ff, wt + OFF_W2 + (size_t)l * DM * DFF, b2 + l * DM, x, x,
            NP, DM, DFF, 0, 0);
    }

    ln_kernel<<<NP / 8, 256>>>(x, lnfs, lnfb, h, DM);
    hgemm<<<dim3(VV / 128, NP / 128), 256, GEMM_SMEM>>>(
        h, wt + OFF_WH, bh, nullptr, out, NP, VV, DM, 0, 0);
    loss_row_kernel<<<NP, 256>>>(out, tgt);
    if (out_size > NP * VV)
        loss_final_kernel<<<1, 256>>>(out + (size_t)NP * VV);
}

// round 7
// speedup vs baseline: 3.9335x; 1.0140x over previous
#include <cuda_runtime.h>
#include <math.h>
#include <stdint.h>

// ---------------------------------------------------------------------------
// Model dims
// ---------------------------------------------------------------------------
#define NP   4096
#define BB   4
#define TT   1024
#define DM   1024
#define HH   16
#define HS   64
#define DFF  4096
#define LL   6
#define VV   32000
#define DBK  64
#define DIN  1088
#define QKVN 3072

// Weight arena offsets (elements)
#define OFF_QKV 0ull
#define OFF_WO  18874368ull
#define OFF_W1  25165824ull
#define OFF_W2  51904512ull
#define OFF_WH  77070336ull
#define WT_TOTAL 109838336ull

// Fused transpose tile counts (64x64 tiles)
#define TIL_SQ   256          /* 1024x1024 weight */
#define TIL_W1   1088         /* K=1088(17) x N=4096(64) */
#define TIL_W2   1024         /* K=4096(64) x N=1024(16) */
#define TIL_LAYER (4 * TIL_SQ + TIL_W1 + TIL_W2)   /* 3136 */
#define TIL_WH   8000         /* K=1024(16) x N=32000(500) */
#define TIL_TOTAL (LL * TIL_LAYER + TIL_WH)        /* 26816 */

// ---------------------------------------------------------------------------
// Scratch
// ---------------------------------------------------------------------------
__device__ __align__(128) float g_x  [NP * DM];
__device__ __align__(128) float g_h  [NP * DM];
__device__ __align__(128) float g_qkv[NP * QKVN];
__device__ __align__(128) float g_ao [NP * DM];
__device__ __align__(128) float g_h2 [NP * DIN];
__device__ __align__(128) float g_ff [NP * DFF];
__device__ __align__(128) float g_wt [WT_TOTAL];
__device__ float g_rowloss[NP];

// ---------------------------------------------------------------------------
// Helpers
// ---------------------------------------------------------------------------
__device__ __forceinline__ uint32_t smem_u32(const void* p) {
    uint32_t a;
    asm("{ .reg .u64 t; cvta.to.shared.u64 t, %1; cvt.u32.u64 %0, t; }"
        : "=r"(a) : "l"(p));
    return a;
}

__device__ __forceinline__ float rtf32(float x) {
    uint32_t u;
    asm("cvt.rna.tf32.f32 %0, %1;" : "=r"(u) : "f"(x));
    return __uint_as_float(u);
}

__device__ __forceinline__ void cp16(uint32_t dst, const void* src) {
    asm volatile("cp.async.cg.shared.global [%0], [%1], 16;" ::"r"(dst), "l"(src));
}

#define LDSM4(r, a)                                                            \
    asm volatile("ldmatrix.sync.aligned.m8n8.x4.shared.b16 {%0,%1,%2,%3}, [%4];" \
                 : "=r"((r)[0]), "=r"((r)[1]), "=r"((r)[2]), "=r"((r)[3])      \
                 : "r"(a))

#define MMA_TF32(d, a, b)                                                      \
    asm volatile(                                                              \
        "mma.sync.aligned.m16n8k8.row.col.f32.tf32.tf32.f32 "                  \
        "{%0,%1,%2,%3}, {%4,%5,%6,%7}, {%8,%9}, {%0,%1,%2,%3};\n"              \
        : "+f"(d[0]), "+f"(d[1]), "+f"(d[2]), "+f"(d[3])                       \
        : "r"(a[0]), "r"(a[1]), "r"(a[2]), "r"(a[3]), "r"(b[0]), "r"(b[1]))

__device__ __forceinline__ float warpSum(float v) {
#pragma unroll
    for (int o = 16; o; o >>= 1) v += __shfl_xor_sync(0xffffffffu, v, o);
    return v;
}
__device__ __forceinline__ float warpMax(float v) {
#pragma unroll
    for (int o = 16; o; o >>= 1) v = fmaxf(v, __shfl_xor_sync(0xffffffffu, v, o));
    return v;
}

__device__ __forceinline__ float blockReduceSum(float v) {
    __shared__ float sm[33];
    int lane = threadIdx.x & 31, w = threadIdx.x >> 5;
    v = warpSum(v);
    if (lane == 0) sm[w] = v;
    __syncthreads();
    if (w == 0) {
        v = (lane < (blockDim.x >> 5)) ? sm[lane] : 0.f;
        v = warpSum(v);
        if (lane == 0) sm[32] = v;
    }
    __syncthreads();
    return sm[32];
}
__device__ __forceinline__ float blockReduceMax(float v) {
    __shared__ float sm[33];
    int lane = threadIdx.x & 31, w = threadIdx.x >> 5;
    v = warpMax(v);
    if (lane == 0) sm[w] = v;
    __syncthreads();
    if (w == 0) {
        v = (lane < (blockDim.x >> 5)) ? sm[lane] : -1e30f;
        v = warpMax(v);
        if (lane == 0) sm[32] = v;
    }
    __syncthreads();
    return sm[32];
}

// ---------------------------------------------------------------------------
// Elementwise kernels
// ---------------------------------------------------------------------------
__global__ void embed_kernel(const int* __restrict__ idx,
                             const float* __restrict__ tok,
                             const float* __restrict__ pos) {
    int gid = blockIdx.x * 256 + threadIdx.x;       // over NP*DM/4
    int n = gid >> 8, c4 = (gid & 255) * 4;
    int t = n & (TT - 1);
    const float4 a = *(const float4*)(tok + (size_t)idx[n] * DM + c4);
    const float4 b = *(const float4*)(pos + (size_t)t * DM + c4);
    float4 o;
    o.x = a.x + b.x; o.y = a.y + b.y; o.z = a.z + b.z; o.w = a.w + b.w;
    *(float4*)(g_x + (size_t)n * DM + c4) = o;
}

__global__ void book_kernel(const int* __restrict__ ibx,
                            const float* __restrict__ book) {
    int gid = blockIdx.x * 256 + threadIdx.x;   // NP*DBK
    int n = gid >> 6, d = gid & 63, b = n >> 10;
    g_h2[(size_t)n * DIN + DM + d] = rtf32(book[ibx[b] * DBK + d]);
}

// LayerNorm: warp per row, shfl-only reductions, float4 I/O.
__global__ __launch_bounds__(256) void ln_kernel(
    const float* __restrict__ x, const float* __restrict__ sc,
    const float* __restrict__ bi, float* __restrict__ y, int ldo) {
    int warp = threadIdx.x >> 5, lane = threadIdx.x & 31;
    int row = blockIdx.x * 8 + warp;
    const float4* xr = (const float4*)(x + (size_t)row * DM);
    float4 v[8];
    float sum = 0.f;
#pragma unroll
    for (int i = 0; i < 8; i++) {
        v[i] = xr[i * 32 + lane];
        sum += v[i].x + v[i].y + v[i].z + v[i].w;
    }
    float mu = warpSum(sum) * (1.f / DM);
    float sq = 0.f;
#pragma unroll
    for (int i = 0; i < 8; i++) {
        float dx = v[i].x - mu, dy = v[i].y - mu;
        float dz = v[i].z - mu, dw = v[i].w - mu;
        sq += dx * dx + dy * dy + dz * dz + dw * dw;
    }
    float rstd = rsqrtf(warpSum(sq) * (1.f / DM) + 1e-5f);
#pragma unroll
    for (int i = 0; i < 8; i++) {
        int c4 = i * 32 + lane;
        float4 s4 = ((const float4*)sc)[c4];
        float4 b4 = ((const float4*)bi)[c4];
        float4 o;
        o.x = rtf32((v[i].x - mu) * rstd * s4.x + b4.x);
        o.y = rtf32((v[i].y - mu) * rstd * s4.y + b4.y);
        o.z = rtf32((v[i].z - mu) * rstd * s4.z + b4.z);
        o.w = rtf32((v[i].w - mu) * rstd * s4.w + b4.w);
        *(float4*)(y + (size_t)row * ldo + c4 * 4) = o;
    }
}

// ---------------------------------------------------------------------------
// Fused weight transpose + tf32 round: ALL weights in ONE launch.
// Each block does one 64x64 tile: W[K][N] (k0,n0) -> Wt[N][K].
// ---------------------------------------------------------------------------
__device__ __forceinline__ void wtr_tile(const float* __restrict__ W,
                                         float* __restrict__ Wt, int K, int N,
                                         int tile) {
    __shared__ float s[64][65];
    int tiles_n = N >> 6;
    int n0 = (tile % tiles_n) << 6;
    int k0 = (tile / tiles_n) << 6;
    int t = threadIdx.x;
    int kk = t >> 4, nn4 = (t & 15) * 4;
#pragma unroll
    for (int i = 0; i < 4; i++) {
        int k = kk + 16 * i;
        float4 w = *(const float4*)(W + (size_t)(k0 + k) * N + n0 + nn4);
        s[nn4 + 0][k] = w.x;
        s[nn4 + 1][k] = w.y;
        s[nn4 + 2][k] = w.z;
        s[nn4 + 3][k] = w.w;
    }
    __syncthreads();
    int k4 = (t & 15) * 4;
#pragma unroll
    for (int i = 0; i < 4; i++) {
        int n = (t >> 4) + 16 * i;
        float4 o;
        o.x = rtf32(s[n][k4 + 0]);
        o.y = rtf32(s[n][k4 + 1]);
        o.z = rtf32(s[n][k4 + 2]);
        o.w = rtf32(s[n][k4 + 3]);
        *(float4*)(Wt + (size_t)(n0 + n) * K + k0 + k4) = o;
    }
}

__global__ __launch_bounds__(256) void wtr_all_kernel(
    const float* __restrict__ Wq, const float* __restrict__ Wk,
    const float* __restrict__ Wv, const float* __restrict__ Wo,
    const float* __restrict__ W1, const float* __restrict__ W2,
    const float* __restrict__ Wh, float* __restrict__ wt) {
    int b = blockIdx.x;
    if (b < LL * TIL_LAYER) {
        int l = b / TIL_LAYER, r = b % TIL_LAYER;
        if (r < 4 * TIL_SQ) {
            int w = r >> 8, tile = r & 255;
            const float* src;
            float* dst;
            size_t lofs = (size_t)l * DM * DM;
            if (w == 0) {
                src = Wq + lofs;
                dst = wt + OFF_QKV + (size_t)l * 3 * DM * DM;
            } else if (w == 1) {
                src = Wk + lofs;
                dst = wt + OFF_QKV + (size_t)l * 3 * DM * DM + (size_t)DM * DM;
            } else if (w == 2) {
                src = Wv + lofs;
                dst = wt + OFF_QKV + (size_t)l * 3 * DM * DM + 2ull * DM * DM;
            } else {
                src = Wo + lofs;
                dst = wt + OFF_WO + lofs;
            }
            wtr_tile(src, dst, DM, DM, tile);
        } else if (r < 4 * TIL_SQ + TIL_W1) {
            wtr_tile(W1 + (size_t)l * DIN * DFF, wt + OFF_W1 + (size_t)l * DFF * DIN,
                     DIN, DFF, r - 4 * TIL_SQ);
        } else {
            wtr_tile(W2 + (size_t)l * DFF * DM, wt + OFF_W2 + (size_t)l * DM * DFF,
                     DFF, DM, r - 4 * TIL_SQ - TIL_W1);
        }
    } else {
        wtr_tile(Wh, wt + OFF_WH, DM, VV, b - LL * TIL_LAYER);
    }
}

// ---------------------------------------------------------------------------
// tf32 mma.sync GEMM with ldmatrix fragment loads (unchanged).
// ---------------------------------------------------------------------------
#define STG 32768
#define GEMM_SMEM (3 * STG)

__global__ __launch_bounds__(256, 2) void hgemm(
    const float* __restrict__ A, const float* __restrict__ Bt,
    const float* __restrict__ bias, const float* __restrict__ res,
    float* __restrict__ C, int M, int N, int K, int relu, int rnd) {
    extern __shared__ __align__(1024) char smem[];
    const uint32_t sb = smem_u32(smem);
    const int tid = threadIdx.x, lane = tid & 31, wid = tid >> 5;
    const int m0 = blockIdx.y * 128, n0 = blockIdx.x * 128;
    const int wm = (wid >> 1) * 32, wn = (wid & 1) * 64;

    const int lrow = tid >> 3, lu = tid & 7;
    const float* srcA = A + (size_t)(m0 + lrow) * K + lu * 4;
    const float* srcB = Bt + (size_t)(n0 + lrow) * K + lu * 4;
    const uint32_t d0 = (uint32_t)lrow * 128 + (((uint32_t)(lu ^ (lrow & 7))) << 4);

    const uint32_t asel = lane >> 4;
    const uint32_t bsel = (lane >> 3) & 1;
    const uint32_t swz = lane & 7;
    const uint32_t a_ro = (uint32_t)(wm + (lane & 7) + ((lane >> 3) & 1) * 8) * 128;
    const uint32_t b_ro = (uint32_t)(wn + (lane & 7) + (lane >> 4) * 8) * 128;

    float acc[2][8][4];
#pragma unroll
    for (int i = 0; i < 2; i++)
#pragma unroll
        for (int j = 0; j < 8; j++)
#pragma unroll
            for (int c = 0; c < 4; c++) acc[i][j][c] = 0.f;

    const int KT = K >> 5;

#define LOADC(s, kof)                                                          \
    do {                                                                       \
        uint32_t bA = sb + (uint32_t)(s) * STG;                                \
        uint32_t bB = bA + 16384;                                              \
        const float* pa = srcA + (kof);                                        \
        const float* pb = srcB + (kof);                                        \
        _Pragma("unroll") for (int ii = 0; ii < 4; ii++)                       \
            cp16(bA + d0 + ii * 4096, pa + (size_t)ii * 32 * K);               \
        _Pragma("unroll") for (int ii = 0; ii < 4; ii++)                       \
            cp16(bB + d0 + ii * 4096, pb + (size_t)ii * 32 * K);               \
        asm volatile("cp.async.commit_group;" ::: "memory");                   \
    } while (0)

    LOADC(0, 0);
    LOADC(1, 32);

    int stage = 0;
    for (int i = 0; i < KT; i++) {
        if (i < KT - 1)
            asm volatile("cp.async.wait_group 1;" ::: "memory");
        else
            asm volatile("cp.async.wait_group 0;" ::: "memory");
        __syncthreads();
        if (i + 2 < KT) {
            int ns = stage + 2;
            if (ns >= 3) ns -= 3;
            LOADC(ns, (size_t)(i + 2) * 32);
        }
        const uint32_t sA = sb + (uint32_t)stage * STG;
        const uint32_t sB = sA + 16384;
#pragma unroll
        for (int ks = 0; ks < 4; ks++) {
            const uint32_t va = ((2u * ks + asel) ^ swz) << 4;
            const uint32_t vb = ((2u * ks + bsel) ^ swz) << 4;
            uint32_t af[2][4];
            LDSM4(af[0], sA + a_ro + va);
            LDSM4(af[1], sA + a_ro + 2048 + va);
            uint32_t bf[8][2];
#pragma unroll
            for (int nb = 0; nb < 4; nb++) {
                uint32_t r[4];
                LDSM4(r, sB + b_ro + nb * 2048 + vb);
                bf[2 * nb][0] = r[0]; bf[2 * nb][1] = r[1];
                bf[2 * nb + 1][0] = r[2]; bf[2 * nb + 1][1] = r[3];
            }
#pragma unroll
            for (int ii = 0; ii < 2; ii++)
#pragma unroll
                for (int j = 0; j < 8; j++) MMA_TF32(acc[ii][j], af[ii], bf[j]);
        }
        stage++;
        if (stage == 3) stage = 0;
    }

#pragma unroll
    for (int i = 0; i < 2; i++) {
        int r0 = m0 + wm + i * 16 + (lane >> 2);
#pragma unroll
        for (int j = 0; j < 8; j++) {
            int c0 = n0 + wn + j * 8 + (lane & 3) * 2;
            float v0 = acc[i][j][0], v1 = acc[i][j][1];
            float v2 = acc[i][j][2], v3 = acc[i][j][3];
            if (bias) {
                float b0 = bias[c0], b1 = bias[c0 + 1];
                v0 += b0; v1 += b1; v2 += b0; v3 += b1;
            }
            if (relu) {
                v0 = fmaxf(v0, 0.f); v1 = fmaxf(v1, 0.f);
                v2 = fmaxf(v2, 0.f); v3 = fmaxf(v3, 0.f);
            }
            size_t o0 = (size_t)r0 * N + c0;
            size_t o1 = (size_t)(r0 + 8) * N + c0;
            if (res) {
                v0 += res[o0]; v1 += res[o0 + 1];
                v2 += res[o1]; v3 += res[o1 + 1];
            }
            if (rnd) {
                v0 = rtf32(v0); v1 = rtf32(v1);
                v2 = rtf32(v2); v3 = rtf32(v3);
            }
            C[o0] = v0; C[o0 + 1] = v1;
            C[o1] = v2; C[o1 + 1] = v3;
        }
    }
#undef LOADC
}

// ---------------------------------------------------------------------------
// Flash attention (fp32 SIMT), q/k/v from fused buffer (stride QKVN),
// output tf32-rounded into g_ao (stride DM).
// ---------------------------------------------------------------------------
#define ATTN_SMEM ((2 * 64 * 65 + 64 * 64) * 4)

__global__ __launch_bounds__(256) void attn_kernel(const float* __restrict__ qkv) {
    extern __shared__ float sm[];
    float* Qs = sm;
    float* Ks = sm + 64 * 65;
    float* Vs = sm + 2 * 64 * 65;

    const float* q = qkv;
    const float* k = qkv + 1024;
    const float* v = qkv + 2048;

    int qt = blockIdx.x, h = blockIdx.y, b = blockIdx.z;
    int tid = threadIdx.x, tx = tid & 15, ty = tid >> 4;
    int rb = b * TT;
    int colbase = h * HS;

#pragma unroll
    for (int it = 0; it < 4; it++) {
        int lin = it * 1024 + tid * 4;
        int r = lin >> 6, c = lin & 63;
        float4 t4 = *(const float4*)(q + (size_t)(rb + qt * 64 + r) * QKVN + colbase + c);
        Qs[r * 65 + c + 0] = t4.x; Qs[r * 65 + c + 1] = t4.y;
        Qs[r * 65 + c + 2] = t4.z; Qs[r * 65 + c + 3] = t4.w;
    }

    float m_i[4], l_i[4], oacc[4][4];
#pragma unroll
    for (int i = 0; i < 4; i++) {
        m_i[i] = -1e30f; l_i[i] = 0.f;
#pragma unroll
        for (int j = 0; j < 4; j++) oacc[i][j] = 0.f;
    }

    for (int jt = 0; jt <= qt; jt++) {
        __syncthreads();
#pragma unroll
        for (int it = 0; it < 4; it++) {
            int lin = it * 1024 + tid * 4;
            int r = lin >> 6, c = lin & 63;
            size_t goff = (size_t)(rb + jt * 64 + r) * QKVN + colbase + c;
            float4 k4 = *(const float4*)(k + goff);
            Ks[r * 65 + c + 0] = k4.x; Ks[r * 65 + c + 1] = k4.y;
            Ks[r * 65 + c + 2] = k4.z; Ks[r * 65 + c + 3] = k4.w;
            float4 v4 = *(const float4*)(v + goff);
            *(float4*)&Vs[r * 64 + c] = v4;
        }
        __syncthreads();

        float s[4][4];
#pragma unroll
        for (int i = 0; i < 4; i++)
#pragma unroll
            for (int j = 0; j < 4; j++) s[i][j] = 0.f;
        for (int d = 0; d < 64; d++) {
            float ar[4], br[4];
#pragma unroll
            for (int i = 0; i < 4; i++) ar[i] = Qs[(ty * 4 + i) * 65 + d];
#pragma unroll
            for (int j = 0; j < 4; j++) br[j] = Ks[(tx * 4 + j) * 65 + d];
#pragma unroll
            for (int i = 0; i < 4; i++)
#pragma unroll
                for (int j = 0; j < 4; j++) s[i][j] += ar[i] * br[j];
        }
#pragma unroll
        for (int i = 0; i < 4; i++) {
            int qi = qt * 64 + ty * 4 + i;
#pragma unroll
            for (int j = 0; j < 4; j++) {
                int kj = jt * 64 + tx * 4 + j;
                s[i][j] = (kj <= qi) ? s[i][j] * 0.125f : -1e30f;
            }
        }
        float corr[4];
#pragma unroll
        for (int i = 0; i < 4; i++) {
            float mx = fmaxf(fmaxf(s[i][0], s[i][1]), fmaxf(s[i][2], s[i][3]));
#pragma unroll
            for (int off = 8; off; off >>= 1)
                mx = fmaxf(mx, __shfl_xor_sync(0xffffffffu, mx, off));
            float mnew = fmaxf(m_i[i], mx);
            float ls = 0.f;
#pragma unroll
            for (int j = 0; j < 4; j++) {
                s[i][j] = __expf(s[i][j] - mnew);
                ls += s[i][j];
            }
#pragma unroll
            for (int off = 8; off; off >>= 1)
                ls += __shfl_xor_sync(0xffffffffu, ls, off);
            corr[i] = __expf(m_i[i] - mnew);
            l_i[i] = l_i[i] * corr[i] + ls;
            m_i[i] = mnew;
        }
        __syncthreads();
#pragma unroll
        for (int i = 0; i < 4; i++)
#pragma unroll
            for (int j = 0; j < 4; j++)
                Ks[(ty * 4 + i) * 65 + tx * 4 + j] = s[i][j];
        __syncthreads();
#pragma unroll
        for (int i = 0; i < 4; i++)
#pragma unroll
            for (int j = 0; j < 4; j++) oacc[i][j] *= corr[i];
        for (int kk = 0; kk < 64; kk++) {
            float ar[4], br[4];
#pragma unroll
            for (int i = 0; i < 4; i++) ar[i] = Ks[(ty * 4 + i) * 65 + kk];
#pragma unroll
            for (int j = 0; j < 4; j++) br[j] = Vs[kk * 64 + tx * 4 + j];
#pragma unroll
            for (int i = 0; i < 4; i++)
#pragma unroll
                for (int j = 0; j < 4; j++) oacc[i][j] += ar[i] * br[j];
        }
    }

#pragma unroll
    for (int i = 0; i < 4; i++) {
        float inv = 1.f / l_i[i];
        size_t rbase = (size_t)(rb + qt * 64 + ty * 4 + i) * DM + colbase + tx * 4;
        float4 o;
        o.x = rtf32(oacc[i][0] * inv);
        o.y = rtf32(oacc[i][1] * inv);
        o.z = rtf32(oacc[i][2] * inv);
        o.w = rtf32(oacc[i][3] * inv);
        *(float4*)&g_ao[rbase] = o;
    }
}

// ---------------------------------------------------------------------------
// Loss: single-pass online softmax per row, then deterministic mean
// ---------------------------------------------------------------------------
__global__ __launch_bounds__(256) void loss_row_kernel(const float* __restrict__ logits,
                                                       const int* __restrict__ targets) {
    int row = blockIdx.x, tid = threadIdx.x;
    const float* lr = logits + (size_t)row * VV;
    float m = -1e30f, s = 0.f;
    for (int c = tid; c < VV; c += 256) {
        float v = lr[c];
        float nm = fmaxf(m, v);
        s = s * __expf(m - nm) + __expf(v - nm);
        m = nm;
    }
    float M = blockReduceMax(m);
    s *= __expf(m - M);
    float S = blockReduceSum(s);
    if (tid == 0) g_rowloss[row] = (M + logf(S)) - lr[targets[row]];
}

__global__ __launch_bounds__(256) void loss_final_kernel(float* __restrict__ out) {
    float s = 0.f;
    for (int i = threadIdx.x; i < NP; i += 256) s += g_rowloss[i];
    s = blockReduceSum(s);
    if (threadIdx.x == 0) out[0] = s * (1.f / NP);
}

// ---------------------------------------------------------------------------
// Host launcher
// ---------------------------------------------------------------------------
extern "C" void kernel_launch(void* const* d_in, const int* in_sizes, int n_in,
                              void* d_out, int out_size) {
    const int*   idx  = (const int*)d_in[0];
    const int*   ibx  = (const int*)d_in[1];
    const int*   tgt  = (const int*)d_in[2];
    const float* tok  = (const float*)d_in[3];
    const float* pos  = (const float*)d_in[4];
    const float* book = (const float*)d_in[5];
    const float* Wq   = (const float*)d_in[6];
    const float* Wk   = (const float*)d_in[7];
    const float* Wv   = (const float*)d_in[8];
    const float* Wo   = (const float*)d_in[9];
    const float* bo   = (const float*)d_in[10];
    const float* ln1s = (const float*)d_in[11];
    const float* ln1b = (const float*)d_in[12];
    const float* ln2s = (const float*)d_in[13];
    const float* ln2b = (const float*)d_in[14];
    const float* W1   = (const float*)d_in[15];
    const float* b1   = (const float*)d_in[16];
    const float* W2   = (const float*)d_in[17];
    const float* b2   = (const float*)d_in[18];
    const float* lnfs = (const float*)d_in[19];
    const float* lnfb = (const float*)d_in[20];
    const float* Wh   = (const float*)d_in[21];
    const float* bh   = (const float*)d_in[22];
    float* out = (float*)d_out;

    float *x, *h, *qkv, *ao, *h2, *ff, *wt;
    cudaGetSymbolAddress((void**)&x,   g_x);
    cudaGetSymbolAddress((void**)&h,   g_h);
    cudaGetSymbolAddress((void**)&qkv, g_qkv);
    cudaGetSymbolAddress((void**)&ao,  g_ao);
    cudaGetSymbolAddress((void**)&h2,  g_h2);
    cudaGetSymbolAddress((void**)&ff,  g_ff);
    cudaGetSymbolAddress((void**)&wt,  g_wt);

    cudaFuncSetAttribute(attn_kernel, cudaFuncAttributeMaxDynamicSharedMemorySize,
                         ATTN_SMEM);
    cudaFuncSetAttribute(hgemm, cudaFuncAttributeMaxDynamicSharedMemorySize,
                         GEMM_SMEM);

    // ---- all weight transposes in ONE launch ----
    wtr_all_kernel<<<TIL_TOTAL, 256>>>(Wq, Wk, Wv, Wo, W1, W2, Wh, wt);

    embed_kernel<<<NP * DM / 1024, 256>>>(idx, tok, pos);
    book_kernel<<<NP * DBK / 256, 256>>>(ibx, book);

    for (int l = 0; l < LL; l++) {
        ln_kernel<<<NP / 8, 256>>>(x, ln1s + l * DM, ln1b + l * DM, h, DM);
        hgemm<<<dim3(QKVN / 128, NP / 128), 256, GEMM_SMEM>>>(
            h, wt + OFF_QKV + (size_t)l * 3 * DM * DM, nullptr, nullptr, qkv,
            NP, QKVN, DM, 0, 0);
        attn_kernel<<<dim3(TT / 64, HH, BB), 256, ATTN_SMEM>>>(qkv);
        hgemm<<<dim3(DM / 128, NP / 128), 256, GEMM_SMEM>>>(
            ao, wt + OFF_WO + (size_t)l * DM * DM, bo + l * DM, x, x,
            NP, DM, DM, 0, 0);
        ln_kernel<<<NP / 8, 256>>>(x, ln2s + l * DM, ln2b + l * DM, h2, DIN);
        hgemm<<<dim3(DFF / 128, NP / 128), 256, GEMM_SMEM>>>(
            h2, wt + OFF_W1 + (size_t)l * DFF * DIN, b1 + l * DFF, nullptr, ff,
            NP, DFF, DIN, 1, 1);
        hgemm<<<dim3(DM / 128, NP / 128), 256, GEMM_SMEM>>>(
            ff, wt + OFF_W2 + (size_t)l * DM * DFF, b2 + l * DM, x, x,
            NP, DM, DFF, 0, 0);
    }

    ln_kernel<<<NP / 8, 256>>>(x, lnfs, lnfb, h, DM);
    hgemm<<<dim3(VV / 128, NP / 128), 256, GEMM_SMEM>>>(
        h, wt + OFF_WH, bh, nullptr, out, NP, VV, DM, 0, 0);
    loss_row_kernel<<<NP, 256>>>(out, tgt);
    if (out_size > NP * VV)
        loss_final_kernel<<<1, 256>>>(out + (size_t)NP * VV);
}

// round 9
// speedup vs baseline: 4.5833x; 1.1652x over previous
#include <cuda_runtime.h>
#include <math.h>
#include <stdint.h>

// ---------------------------------------------------------------------------
// Model dims
// ---------------------------------------------------------------------------
#define NP   4096
#define BB   4
#define TT   1024
#define DM   1024
#define HH   16
#define HS   64
#define DFF  4096
#define LL   6
#define VV   32000
#define DBK  64
#define DIN  1088
#define QKVN 3072
#define ZZ   (BB * HH)          /* 64 (b,h) pairs */

// Weight arena offsets (elements)
#define OFF_QKV 0ull
#define OFF_WO  18874368ull
#define OFF_W1  25165824ull
#define OFF_W2  51904512ull
#define OFF_WH  77070336ull
#define WT_TOTAL 109838336ull

// Fused transpose tile counts (64x64 tiles)
#define TIL_SQ   256
#define TIL_W1   1088
#define TIL_W2   1024
#define TIL_LAYER (4 * TIL_SQ + TIL_W1 + TIL_W2)
#define TIL_WH   8000
#define TIL_TOTAL (LL * TIL_LAYER + TIL_WH)

// ---------------------------------------------------------------------------
// Scratch
// ---------------------------------------------------------------------------
__device__ __align__(128) float g_x  [NP * DM];
__device__ __align__(128) float g_h  [NP * DM];
__device__ __align__(128) float g_qkv[NP * QKVN];
__device__ __align__(128) float g_ao [NP * DM];
__device__ __align__(128) float g_h2 [NP * DIN];
__device__ __align__(128) float g_ff [NP * DFF];
__device__ __align__(128) float g_wt [WT_TOTAL];
__device__ __align__(128) float g_s  [(size_t)ZZ * TT * TT];   // attention scores
__device__ __align__(128) float g_vt [(size_t)ZZ * HS * TT];   // V^T per (b,h)
__device__ float g_rowloss[NP];

// ---------------------------------------------------------------------------
// Helpers
// ---------------------------------------------------------------------------
__device__ __forceinline__ uint32_t smem_u32(const void* p) {
    uint32_t a;
    asm("{ .reg .u64 t; cvta.to.shared.u64 t, %1; cvt.u32.u64 %0, t; }"
        : "=r"(a) : "l"(p));
    return a;
}

__device__ __forceinline__ float rtf32(float x) {
    uint32_t u;
    asm("cvt.rna.tf32.f32 %0, %1;" : "=r"(u) : "f"(x));
    return __uint_as_float(u);
}

__device__ __forceinline__ void cp16(uint32_t dst, const void* src) {
    asm volatile("cp.async.cg.shared.global [%0], [%1], 16;" ::"r"(dst), "l"(src));
}

#define LDSM4(r, a)                                                            \
    asm volatile("ldmatrix.sync.aligned.m8n8.x4.shared.b16 {%0,%1,%2,%3}, [%4];" \
                 : "=r"((r)[0]), "=r"((r)[1]), "=r"((r)[2]), "=r"((r)[3])      \
                 : "r"(a))

#define MMA_TF32(d, a, b)                                                      \
    asm volatile(                                                              \
        "mma.sync.aligned.m16n8k8.row.col.f32.tf32.tf32.f32 "                  \
        "{%0,%1,%2,%3}, {%4,%5,%6,%7}, {%8,%9}, {%0,%1,%2,%3};\n"              \
        : "+f"(d[0]), "+f"(d[1]), "+f"(d[2]), "+f"(d[3])                       \
        : "r"(a[0]), "r"(a[1]), "r"(a[2]), "r"(a[3]), "r"(b[0]), "r"(b[1]))

__device__ __forceinline__ float warpSum(float v) {
#pragma unroll
    for (int o = 16; o; o >>= 1) v += __shfl_xor_sync(0xffffffffu, v, o);
    return v;
}
__device__ __forceinline__ float warpMax(float v) {
#pragma unroll
    for (int o = 16; o; o >>= 1) v = fmaxf(v, __shfl_xor_sync(0xffffffffu, v, o));
    return v;
}

__device__ __forceinline__ float blockReduceSum(float v) {
    __shared__ float sm[33];
    int lane = threadIdx.x & 31, w = threadIdx.x >> 5;
    v = warpSum(v);
    if (lane == 0) sm[w] = v;
    __syncthreads();
    if (w == 0) {
        v = (lane < (blockDim.x >> 5)) ? sm[lane] : 0.f;
        v = warpSum(v);
        if (lane == 0) sm[32] = v;
    }
    __syncthreads();
    return sm[32];
}
__device__ __forceinline__ float blockReduceMax(float v) {
    __shared__ float sm[33];
    int lane = threadIdx.x & 31, w = threadIdx.x >> 5;
    v = warpMax(v);
    if (lane == 0) sm[w] = v;
    __syncthreads();
    if (w == 0) {
        v = (lane < (blockDim.x >> 5)) ? sm[lane] : -1e30f;
        v = warpMax(v);
        if (lane == 0) sm[32] = v;
    }
    __syncthreads();
    return sm[32];
}

// ---------------------------------------------------------------------------
// Elementwise kernels
// ---------------------------------------------------------------------------
__global__ void embed_kernel(const int* __restrict__ idx,
                             const float* __restrict__ tok,
                             const float* __restrict__ pos) {
    int gid = blockIdx.x * 256 + threadIdx.x;
    int n = gid >> 8, c4 = (gid & 255) * 4;
    int t = n & (TT - 1);
    const float4 a = *(const float4*)(tok + (size_t)idx[n] * DM + c4);
    const float4 b = *(const float4*)(pos + (size_t)t * DM + c4);
    float4 o;
    o.x = a.x + b.x; o.y = a.y + b.y; o.z = a.z + b.z; o.w = a.w + b.w;
    *(float4*)(g_x + (size_t)n * DM + c4) = o;
}

__global__ void book_kernel(const int* __restrict__ ibx,
                            const float* __restrict__ book) {
    int gid = blockIdx.x * 256 + threadIdx.x;
    int n = gid >> 6, d = gid & 63, b = n >> 10;
    g_h2[(size_t)n * DIN + DM + d] = rtf32(book[ibx[b] * DBK + d]);
}

// LayerNorm: warp per row, 4 rows/block.
__global__ __launch_bounds__(128) void ln_kernel(
    const float* __restrict__ x, const float* __restrict__ sc,
    const float* __restrict__ bi, float* __restrict__ y, int ldo) {
    int warp = threadIdx.x >> 5, lane = threadIdx.x & 31;
    int row = blockIdx.x * 4 + warp;
    const float4* xr = (const float4*)(x + (size_t)row * DM);
    float4 v[8];
    float sum = 0.f;
#pragma unroll
    for (int i = 0; i < 8; i++) {
        v[i] = xr[i * 32 + lane];
        sum += v[i].x + v[i].y + v[i].z + v[i].w;
    }
    float mu = warpSum(sum) * (1.f / DM);
    float sq = 0.f;
#pragma unroll
    for (int i = 0; i < 8; i++) {
        float dx = v[i].x - mu, dy = v[i].y - mu;
        float dz = v[i].z - mu, dw = v[i].w - mu;
        sq += dx * dx + dy * dy + dz * dz + dw * dw;
    }
    float rstd = rsqrtf(warpSum(sq) * (1.f / DM) + 1e-5f);
#pragma unroll
    for (int i = 0; i < 8; i++) {
        int c4 = i * 32 + lane;
        float4 s4 = ((const float4*)sc)[c4];
        float4 b4 = ((const float4*)bi)[c4];
        float4 o;
        o.x = rtf32((v[i].x - mu) * rstd * s4.x + b4.x);
        o.y = rtf32((v[i].y - mu) * rstd * s4.y + b4.y);
        o.z = rtf32((v[i].z - mu) * rstd * s4.z + b4.z);
        o.w = rtf32((v[i].w - mu) * rstd * s4.w + b4.w);
        *(float4*)(y + (size_t)row * ldo + c4 * 4) = o;
    }
}

// ---------------------------------------------------------------------------
// Fused weight transpose + tf32 round (one launch for all weights)
// ---------------------------------------------------------------------------
__device__ __forceinline__ void wtr_tile(const float* __restrict__ W,
                                         float* __restrict__ Wt, int K, int N,
                                         int tile) {
    __shared__ float s[64][65];
    int tiles_n = N >> 6;
    int n0 = (tile % tiles_n) << 6;
    int k0 = (tile / tiles_n) << 6;
    int t = threadIdx.x;
    int kk = t >> 4, nn4 = (t & 15) * 4;
#pragma unroll
    for (int i = 0; i < 4; i++) {
        int k = kk + 16 * i;
        float4 w = *(const float4*)(W + (size_t)(k0 + k) * N + n0 + nn4);
        s[nn4 + 0][k] = w.x;
        s[nn4 + 1][k] = w.y;
        s[nn4 + 2][k] = w.z;
        s[nn4 + 3][k] = w.w;
    }
    __syncthreads();
    int k4 = (t & 15) * 4;
#pragma unroll
    for (int i = 0; i < 4; i++) {
        int n = (t >> 4) + 16 * i;
        float4 o;
        o.x = rtf32(s[n][k4 + 0]);
        o.y = rtf32(s[n][k4 + 1]);
        o.z = rtf32(s[n][k4 + 2]);
        o.w = rtf32(s[n][k4 + 3]);
        *(float4*)(Wt + (size_t)(n0 + n) * K + k0 + k4) = o;
    }
}

__global__ __launch_bounds__(256) void wtr_all_kernel(
    const float* __restrict__ Wq, const float* __restrict__ Wk,
    const float* __restrict__ Wv, const float* __restrict__ Wo,
    const float* __restrict__ W1, const float* __restrict__ W2,
    const float* __restrict__ Wh, float* __restrict__ wt) {
    int b = blockIdx.x;
    if (b < LL * TIL_LAYER) {
        int l = b / TIL_LAYER, r = b % TIL_LAYER;
        if (r < 4 * TIL_SQ) {
            int w = r >> 8, tile = r & 255;
            const float* src;
            float* dst;
            size_t lofs = (size_t)l * DM * DM;
            if (w == 0) {
                src = Wq + lofs;
                dst = wt + OFF_QKV + (size_t)l * 3 * DM * DM;
            } else if (w == 1) {
                src = Wk + lofs;
                dst = wt + OFF_QKV + (size_t)l * 3 * DM * DM + (size_t)DM * DM;
            } else if (w == 2) {
                src = Wv + lofs;
                dst = wt + OFF_QKV + (size_t)l * 3 * DM * DM + 2ull * DM * DM;
            } else {
                src = Wo + lofs;
                dst = wt + OFF_WO + lofs;
            }
            wtr_tile(src, dst, DM, DM, tile);
        } else if (r < 4 * TIL_SQ + TIL_W1) {
            wtr_tile(W1 + (size_t)l * DIN * DFF, wt + OFF_W1 + (size_t)l * DFF * DIN,
                     DIN, DFF, r - 4 * TIL_SQ);
        } else {
            wtr_tile(W2 + (size_t)l * DFF * DM, wt + OFF_W2 + (size_t)l * DM * DFF,
                     DFF, DM, r - 4 * TIL_SQ - TIL_W1);
        }
    } else {
        wtr_tile(Wh, wt + OFF_WH, DM, VV, b - LL * TIL_LAYER);
    }
}

// V^T: qkv V-part -> g_vt[z][d][j]  (z = b*16+h)
__global__ __launch_bounds__(256) void vt_kernel() {
    __shared__ float s[64][65];
    int z = blockIdx.y, jt = blockIdx.x;
    int b = z >> 4, h = z & 15;
    int t = threadIdx.x;
    int rr = t >> 4, c4 = (t & 15) * 4;
#pragma unroll
    for (int i = 0; i < 4; i++) {
        int r = rr + 16 * i;
        const float4 w = *(const float4*)(g_qkv +
            (size_t)(b * TT + jt * 64 + r) * QKVN + 2048 + h * 64 + c4);
        s[c4 + 0][r] = w.x;
        s[c4 + 1][r] = w.y;
        s[c4 + 2][r] = w.z;
        s[c4 + 3][r] = w.w;
    }
    __syncthreads();
#pragma unroll
    for (int i = 0; i < 4; i++) {
        int d = rr + 16 * i;
        float4 o;
        o.x = s[d][c4 + 0];
        o.y = s[d][c4 + 1];
        o.z = s[d][c4 + 2];
        o.w = s[d][c4 + 3];
        *(float4*)(g_vt + (size_t)z * (HS * TT) + (size_t)d * TT + jt * 64 + c4) = o;
    }
}

// ---------------------------------------------------------------------------
// tf32 mma.sync GEMM, generalized: row strides lda/ldb, batch-z offsets,
// optional causal block skip. C row stride = N.
// ---------------------------------------------------------------------------
#define STG 32768
#define GEMM_SMEM (3 * STG)

__global__ __launch_bounds__(256, 2) void hgemm(
    const float* __restrict__ A, int lda, size_t zsA1, size_t zsA0,
    const float* __restrict__ Bt, int ldb, size_t zsB1, size_t zsB0,
    const float* __restrict__ bias, const float* __restrict__ res,
    float* __restrict__ C, size_t zsC1, size_t zsC0,
    int M, int N, int K, int relu, int rnd, int causal) {
    extern __shared__ __align__(1024) char smem[];
    const int m0 = blockIdx.y * 128, n0 = blockIdx.x * 128;
    if (causal && n0 > m0 + 127) return;
    const int z1 = blockIdx.z >> 4, z0 = blockIdx.z & 15;
    A += (size_t)z1 * zsA1 + (size_t)z0 * zsA0;
    Bt += (size_t)z1 * zsB1 + (size_t)z0 * zsB0;
    C += (size_t)z1 * zsC1 + (size_t)z0 * zsC0;

    const uint32_t sb = smem_u32(smem);
    const int tid = threadIdx.x, lane = tid & 31, wid = tid >> 5;
    const int wm = (wid >> 1) * 32, wn = (wid & 1) * 64;

    const int lrow = tid >> 3, lu = tid & 7;
    const float* srcA = A + (size_t)(m0 + lrow) * lda + lu * 4;
    const float* srcB = Bt + (size_t)(n0 + lrow) * ldb + lu * 4;
    // 32-row stride per cp.async iteration (matches smem step of 4096 B)
    const size_t rstepA = (size_t)32 * lda, rstepB = (size_t)32 * ldb;
    const uint32_t d0 = (uint32_t)lrow * 128 + (((uint32_t)(lu ^ (lrow & 7))) << 4);

    const uint32_t asel = lane >> 4;
    const uint32_t bsel = (lane >> 3) & 1;
    const uint32_t swz = lane & 7;
    const uint32_t a_ro = (uint32_t)(wm + (lane & 7) + ((lane >> 3) & 1) * 8) * 128;
    const uint32_t b_ro = (uint32_t)(wn + (lane & 7) + (lane >> 4) * 8) * 128;

    float acc[2][8][4];
#pragma unroll
    for (int i = 0; i < 2; i++)
#pragma unroll
        for (int j = 0; j < 8; j++)
#pragma unroll
            for (int c = 0; c < 4; c++) acc[i][j][c] = 0.f;

    const int KT = K >> 5;

#define LOADC(s, kof)                                                          \
    do {                                                                       \
        uint32_t bA = sb + (uint32_t)(s) * STG;                                \
        uint32_t bB = bA + 16384;                                              \
        const float* pa = srcA + (kof);                                        \
        const float* pb = srcB + (kof);                                        \
        _Pragma("unroll") for (int ii = 0; ii < 4; ii++)                       \
            cp16(bA + d0 + ii * 4096, pa + ii * rstepA);                       \
        _Pragma("unroll") for (int ii = 0; ii < 4; ii++)                       \
            cp16(bB + d0 + ii * 4096, pb + ii * rstepB);                       \
        asm volatile("cp.async.commit_group;" ::: "memory");                   \
    } while (0)

    LOADC(0, 0);
    LOADC(1, 32);

    int stage = 0;
    for (int i = 0; i < KT; i++) {
        if (i < KT - 1)
            asm volatile("cp.async.wait_group 1;" ::: "memory");
        else
            asm volatile("cp.async.wait_group 0;" ::: "memory");
        __syncthreads();
        if (i + 2 < KT) {
            int ns = stage + 2;
            if (ns >= 3) ns -= 3;
            LOADC(ns, (size_t)(i + 2) * 32);
        }
        const uint32_t sA = sb + (uint32_t)stage * STG;
        const uint32_t sB = sA + 16384;
#pragma unroll
        for (int ks = 0; ks < 4; ks++) {
            const uint32_t va = ((2u * ks + asel) ^ swz) << 4;
            const uint32_t vb = ((2u * ks + bsel) ^ swz) << 4;
            uint32_t af[2][4];
            LDSM4(af[0], sA + a_ro + va);
            LDSM4(af[1], sA + a_ro + 2048 + va);
            uint32_t bf[8][2];
#pragma unroll
            for (int nb = 0; nb < 4; nb++) {
                uint32_t r[4];
                LDSM4(r, sB + b_ro + nb * 2048 + vb);
                bf[2 * nb][0] = r[0]; bf[2 * nb][1] = r[1];
                bf[2 * nb + 1][0] = r[2]; bf[2 * nb + 1][1] = r[3];
            }
#pragma unroll
            for (int ii = 0; ii < 2; ii++)
#pragma unroll
                for (int j = 0; j < 8; j++) MMA_TF32(acc[ii][j], af[ii], bf[j]);
        }
        stage++;
        if (stage == 3) stage = 0;
    }

#pragma unroll
    for (int i = 0; i < 2; i++) {
        int r0 = m0 + wm + i * 16 + (lane >> 2);
#pragma unroll
        for (int j = 0; j < 8; j++) {
            int c0 = n0 + wn + j * 8 + (lane & 3) * 2;
            float v0 = acc[i][j][0], v1 = acc[i][j][1];
            float v2 = acc[i][j][2], v3 = acc[i][j][3];
            if (bias) {
                float b0 = bias[c0], b1 = bias[c0 + 1];
                v0 += b0; v1 += b1; v2 += b0; v3 += b1;
            }
            if (relu) {
                v0 = fmaxf(v0, 0.f); v1 = fmaxf(v1, 0.f);
                v2 = fmaxf(v2, 0.f); v3 = fmaxf(v3, 0.f);
            }
            size_t o0 = (size_t)r0 * N + c0;
            size_t o1 = (size_t)(r0 + 8) * N + c0;
            if (res) {
                v0 += res[o0]; v1 += res[o0 + 1];
                v2 += res[o1]; v3 += res[o1 + 1];
            }
            if (rnd) {
                v0 = rtf32(v0); v1 = rtf32(v1);
                v2 = rtf32(v2); v3 = rtf32(v3);
            }
            C[o0] = v0; C[o0 + 1] = v1;
            C[o1] = v2; C[o1 + 1] = v3;
        }
    }
#undef LOADC
}

// ---------------------------------------------------------------------------
// Softmax over S rows: warp per row, writes tf32 P in place,
// zero-fills up to the row's 128-aligned width.
// ---------------------------------------------------------------------------
__global__ __launch_bounds__(256) void softmax_kernel() {
    int gid = blockIdx.x * 8 + (threadIdx.x >> 5);
    int lane = threadIdx.x & 31;
    int z = gid >> 10, i = gid & 1023;
    float* sr = g_s + (size_t)z * (TT * TT) + (size_t)i * TT;
    int L = i + 1;
    int W = ((i >> 7) + 1) << 7;
    float m = -1e30f;
    for (int j0 = lane * 4; j0 < W; j0 += 128) {
        float4 v = *(const float4*)(sr + j0);
        if (j0 + 0 < L) m = fmaxf(m, v.x);
        if (j0 + 1 < L) m = fmaxf(m, v.y);
        if (j0 + 2 < L) m = fmaxf(m, v.z);
        if (j0 + 3 < L) m = fmaxf(m, v.w);
    }
    m = warpMax(m) * 0.125f;
    float sum = 0.f;
    for (int j0 = lane * 4; j0 < W; j0 += 128) {
        float4 v = *(const float4*)(sr + j0);
        if (j0 + 0 < L) sum += __expf(v.x * 0.125f - m);
        if (j0 + 1 < L) sum += __expf(v.y * 0.125f - m);
        if (j0 + 2 < L) sum += __expf(v.z * 0.125f - m);
        if (j0 + 3 < L) sum += __expf(v.w * 0.125f - m);
    }
    float inv = 1.f / warpSum(sum);
    for (int j0 = lane * 4; j0 < W; j0 += 128) {
        float4 v = *(const float4*)(sr + j0);
        float4 p;
        p.x = (j0 + 0 < L) ? rtf32(__expf(v.x * 0.125f - m) * inv) : 0.f;
        p.y = (j0 + 1 < L) ? rtf32(__expf(v.y * 0.125f - m) * inv) : 0.f;
        p.z = (j0 + 2 < L) ? rtf32(__expf(v.z * 0.125f - m) * inv) : 0.f;
        p.w = (j0 + 3 < L) ? rtf32(__expf(v.w * 0.125f - m) * inv) : 0.f;
        *(float4*)(sr + j0) = p;
    }
}

// ---------------------------------------------------------------------------
// PV gemm: O[128m x 64n] = P[m,k] * Vt[n,k]^T per (z, m-block), causal
// K truncation. 128 threads, 3-stage cp.async.
// ---------------------------------------------------------------------------
#define PV_STG 24576
#define PV_SMEM (3 * PV_STG)

__global__ __launch_bounds__(128, 2) void pv_gemm() {
    extern __shared__ __align__(1024) char smem[];
    const uint32_t sb = smem_u32(smem);
    const int tid = threadIdx.x, lane = tid & 31, wid = tid >> 5;
    const int mb = blockIdx.x, z = blockIdx.y;
    const int m0 = mb * 128;
    const int KT = (mb + 1) * 4;

    const float* P = g_s + (size_t)z * (TT * TT);
    const float* Vt = g_vt + (size_t)z * (HS * TT);

    const int lrow = tid >> 3, lu = tid & 7;      // lrow 0..15
    const float* srcA = P + (size_t)(m0 + lrow) * TT + lu * 4;
    const float* srcB = Vt + (size_t)lrow * TT + lu * 4;
    const uint32_t d0 = (uint32_t)lrow * 128 + (((uint32_t)(lu ^ (lrow & 7))) << 4);

    const uint32_t asel = lane >> 4;
    const uint32_t bsel = (lane >> 3) & 1;
    const uint32_t swz = lane & 7;
    const int wm = wid * 32;
    const uint32_t a_ro = (uint32_t)(wm + (lane & 7) + ((lane >> 3) & 1) * 8) * 128;
    const uint32_t b_ro = (uint32_t)((lane & 7) + (lane >> 4) * 8) * 128;

    float acc[2][8][4];
#pragma unroll
    for (int i = 0; i < 2; i++)
#pragma unroll
        for (int j = 0; j < 8; j++)
#pragma unroll
            for (int c = 0; c < 4; c++) acc[i][j][c] = 0.f;

#define PLOADC(s, kof)                                                         \
    do {                                                                       \
        uint32_t bA = sb + (uint32_t)(s) * PV_STG;                             \
        uint32_t bB = bA + 16384;                                              \
        const float* pa = srcA + (kof);                                        \
        const float* pb = srcB + (kof);                                        \
        _Pragma("unroll") for (int ii = 0; ii < 8; ii++)                       \
            cp16(bA + d0 + ii * 2048, pa + (size_t)ii * 16 * TT);              \
        _Pragma("unroll") for (int ii = 0; ii < 4; ii++)                       \
            cp16(bB + d0 + ii * 2048, pb + (size_t)ii * 16 * TT);              \
        asm volatile("cp.async.commit_group;" ::: "memory");                   \
    } while (0)

    PLOADC(0, 0);
    PLOADC(1, 32);

    int stage = 0;
    for (int i = 0; i < KT; i++) {
        if (i < KT - 1)
            asm volatile("cp.async.wait_group 1;" ::: "memory");
        else
            asm volatile("cp.async.wait_group 0;" ::: "memory");
        __syncthreads();
        if (i + 2 < KT) {
            int ns = stage + 2;
            if (ns >= 3) ns -= 3;
            PLOADC(ns, (size_t)(i + 2) * 32);
        }
        const uint32_t sA = sb + (uint32_t)stage * PV_STG;
        const uint32_t sB = sA + 16384;
#pragma unroll
        for (int ks = 0; ks < 4; ks++) {
            const uint32_t va = ((2u * ks + asel) ^ swz) << 4;
            const uint32_t vb = ((2u * ks + bsel) ^ swz) << 4;
            uint32_t af[2][4];
            LDSM4(af[0], sA + a_ro + va);
            LDSM4(af[1], sA + a_ro + 2048 + va);
            uint32_t bf[8][2];
#pragma unroll
            for (int nb = 0; nb < 4; nb++) {
                uint32_t r[4];
                LDSM4(r, sB + b_ro + nb * 2048 + vb);
                bf[2 * nb][0] = r[0]; bf[2 * nb][1] = r[1];
                bf[2 * nb + 1][0] = r[2]; bf[2 * nb + 1][1] = r[3];
            }
#pragma unroll
            for (int ii = 0; ii < 2; ii++)
#pragma unroll
                for (int j = 0; j < 8; j++) MMA_TF32(acc[ii][j], af[ii], bf[j]);
        }
        stage++;
        if (stage == 3) stage = 0;
    }

    const int b = z >> 4, h = z & 15;
#pragma unroll
    for (int i = 0; i < 2; i++) {
        int r0 = m0 + wm + i * 16 + (lane >> 2);
        int tok0 = b * TT + r0;
#pragma unroll
        for (int j = 0; j < 8; j++) {
            int c0 = h * 64 + j * 8 + (lane & 3) * 2;
            size_t o0 = (size_t)tok0 * DM + c0;
            size_t o1 = (size_t)(tok0 + 8) * DM + c0;
            g_ao[o0] = rtf32(acc[i][j][0]);
            g_ao[o0 + 1] = rtf32(acc[i][j][1]);
            g_ao[o1] = rtf32(acc[i][j][2]);
            g_ao[o1 + 1] = rtf32(acc[i][j][3]);
        }
    }
#undef PLOADC
}

// ---------------------------------------------------------------------------
// Loss
// ---------------------------------------------------------------------------
__global__ __launch_bounds__(256) void loss_row_kernel(const float* __restrict__ logits,
                                                       const int* __restrict__ targets) {
    int row = blockIdx.x, tid = threadIdx.x;
    const float* lr = logits + (size_t)row * VV;
    float m = -1e30f, s = 0.f;
    for (int c = tid; c < VV; c += 256) {
        float v = lr[c];
        float nm = fmaxf(m, v);
        s = s * __expf(m - nm) + __expf(v - nm);
        m = nm;
    }
    float M = blockReduceMax(m);
    s *= __expf(m - M);
    float S = blockReduceSum(s);
    if (tid == 0) g_rowloss[row] = (M + logf(S)) - lr[targets[row]];
}

__global__ __launch_bounds__(256) void loss_final_kernel(float* __restrict__ out) {
    float s = 0.f;
    for (int i = threadIdx.x; i < NP; i += 256) s += g_rowloss[i];
    s = blockReduceSum(s);
    if (threadIdx.x == 0) out[0] = s * (1.f / NP);
}

// ---------------------------------------------------------------------------
// Host launcher
// ---------------------------------------------------------------------------
extern "C" void kernel_launch(void* const* d_in, const int* in_sizes, int n_in,
                              void* d_out, int out_size) {
    const int*   idx  = (const int*)d_in[0];
    const int*   ibx  = (const int*)d_in[1];
    const int*   tgt  = (const int*)d_in[2];
    const float* tok  = (const float*)d_in[3];
    const float* pos  = (const float*)d_in[4];
    const float* book = (const float*)d_in[5];
    const float* Wq   = (const float*)d_in[6];
    const float* Wk   = (const float*)d_in[7];
    const float* Wv   = (const float*)d_in[8];
    const float* Wo   = (const float*)d_in[9];
    const float* bo   = (const float*)d_in[10];
    const float* ln1s = (const float*)d_in[11];
    const float* ln1b = (const float*)d_in[12];
    const float* ln2s = (const float*)d_in[13];
    const float* ln2b = (const float*)d_in[14];
    const float* W1   = (const float*)d_in[15];
    const float* b1   = (const float*)d_in[16];
    const float* W2   = (const float*)d_in[17];
    const float* b2   = (const float*)d_in[18];
    const float* lnfs = (const float*)d_in[19];
    const float* lnfb = (const float*)d_in[20];
    const float* Wh   = (const float*)d_in[21];
    const float* bh   = (const float*)d_in[22];
    float* out = (float*)d_out;

    float *x, *h, *qkv, *ao, *h2, *ff, *wt, *s_;
    cudaGetSymbolAddress((void**)&x,   g_x);
    cudaGetSymbolAddress((void**)&h,   g_h);
    cudaGetSymbolAddress((void**)&qkv, g_qkv);
    cudaGetSymbolAddress((void**)&ao,  g_ao);
    cudaGetSymbolAddress((void**)&h2,  g_h2);
    cudaGetSymbolAddress((void**)&ff,  g_ff);
    cudaGetSymbolAddress((void**)&wt,  g_wt);
    cudaGetSymbolAddress((void**)&s_,  g_s);

    cudaFuncSetAttribute(hgemm, cudaFuncAttributeMaxDynamicSharedMemorySize,
                         GEMM_SMEM);
    cudaFuncSetAttribute(pv_gemm, cudaFuncAttributeMaxDynamicSharedMemorySize,
                         PV_SMEM);

    wtr_all_kernel<<<TIL_TOTAL, 256>>>(Wq, Wk, Wv, Wo, W1, W2, Wh, wt);
    embed_kernel<<<NP * DM / 1024, 256>>>(idx, tok, pos);
    book_kernel<<<NP * DBK / 256, 256>>>(ibx, book);

    const size_t sAb = (size_t)TT * QKVN;      // per-b stride into qkv rows
    const size_t sCb = (size_t)HH * TT * TT;   // per-b stride into g_s
    for (int l = 0; l < LL; l++) {
        ln_kernel<<<NP / 4, 128>>>(x, ln1s + l * DM, ln1b + l * DM, h, DM);
        hgemm<<<dim3(QKVN / 128, NP / 128, 1), 256, GEMM_SMEM>>>(
            h, DM, 0, 0, wt + OFF_QKV + (size_t)l * 3 * DM * DM, DM, 0, 0,
            nullptr, nullptr, qkv, 0, 0, NP, QKVN, DM, 0, 1, 0);
        vt_kernel<<<dim3(TT / 64, ZZ), 256>>>();
        hgemm<<<dim3(TT / 128, TT / 128, ZZ), 256, GEMM_SMEM>>>(
            qkv, QKVN, sAb, 64, qkv + 1024, QKVN, sAb, 64,
            nullptr, nullptr, s_, sCb, (size_t)TT * TT, TT, TT, HS, 0, 0, 1);
        softmax_kernel<<<ZZ * TT / 8, 256>>>();
        pv_gemm<<<dim3(TT / 128, ZZ), 128, PV_SMEM>>>();
        hgemm<<<dim3(DM / 128, NP / 128, 1), 256, GEMM_SMEM>>>(
            ao, DM, 0, 0, wt + OFF_WO + (size_t)l * DM * DM, DM, 0, 0,
            bo + l * DM, x, x, 0, 0, NP, DM, DM, 0, 0, 0);
        ln_kernel<<<NP / 4, 128>>>(x, ln2s + l * DM, ln2b + l * DM, h2, DIN);
        hgemm<<<dim3(DFF / 128, NP / 128, 1), 256, GEMM_SMEM>>>(
            h2, DIN, 0, 0, wt + OFF_W1 + (size_t)l * DFF * DIN, DIN, 0, 0,
            b1 + l * DFF, nullptr, ff, 0, 0, NP, DFF, DIN, 1, 1, 0);
        hgemm<<<dim3(DM / 128, NP / 128, 1), 256, GEMM_SMEM>>>(
            ff, DFF, 0, 0, wt + OFF_W2 + (size_t)l * DM * DFF, DFF, 0, 0,
            b2 + l * DM, x, x, 0, 0, NP, DM, DFF, 0, 0, 0);
    }

    ln_kernel<<<NP / 4, 128>>>(x, lnfs, lnfb, h, DM);
    hgemm<<<dim3(VV / 128, NP / 128, 1), 256, GEMM_SMEM>>>(
        h, DM, 0, 0, wt + OFF_WH, DM, 0, 0, bh, nullptr, out, 0, 0,
        NP, VV, DM, 0, 0, 0);
    loss_row_kernel<<<NP, 256>>>(out, tgt);
    if (out_size > NP * VV)
        loss_final_kernel<<<1, 256>>>(out + (size_t)NP * VV);
}